// round 2
// baseline (speedup 1.0000x reference)
#include <cuda_runtime.h>

// ---------------------------------------------------------------------------
// ClockworkGRU:
//   Phase A: proj[z] = x @ Wz + bz for z in {W, Wr, Wz}   (3x SGEMM, fp32)
//   Phase B: sequential scan, one CTA per batch element.
// ---------------------------------------------------------------------------

#define GM 32768   // B*SEQ rows
#define GK 512
#define GN 512
#define SEQ_LEN 512
#define NBATCH 64

// Scratch for the three projections: [3][GM][GN] fp32 (static device array;
// heap allocation is forbidden by the harness).
__device__ float g_proj[3ull * GM * GN];

// ---------------- packed f32x2 helpers (doubles fp32 FMA rate on sm_103a) ---
__device__ __forceinline__ unsigned long long pack2(float x, float y) {
    unsigned long long r;
    asm("mov.b64 %0, {%1, %2};" : "=l"(r) : "f"(x), "f"(y));
    return r;
}
__device__ __forceinline__ void fma2(unsigned long long& d,
                                     unsigned long long a,
                                     unsigned long long b) {
    asm("fma.rn.f32x2 %0, %1, %2, %0;" : "+l"(d) : "l"(a), "l"(b));
}
__device__ __forceinline__ float2 unpack2(unsigned long long v) {
    float2 r;
    asm("mov.b64 {%0, %1}, %2;" : "=f"(r.x), "=f"(r.y) : "l"(v));
    return r;
}

__device__ __forceinline__ float sigmoidf_(float x) {
    return 1.0f / (1.0f + __expf(-x));
}

// ---------------------------------------------------------------------------
// GEMM: C[z] = A @ W[z] + bias[z].  BM=BN=128, BK=8, 256 threads, 8x8 micro-
// tile per thread, accumulators packed as f32x2.
// ---------------------------------------------------------------------------
#define BM 128
#define BN 128
#define BKK 8

__global__ void __launch_bounds__(256) gemm3_kernel(
    const float* __restrict__ A,
    const float* __restrict__ W0, const float* __restrict__ b0,
    const float* __restrict__ W1, const float* __restrict__ b1,
    const float* __restrict__ W2, const float* __restrict__ b2)
{
    __shared__ float As[BKK][BM];
    __shared__ float Bs[BKK][BN];

    const int z = blockIdx.z;
    const float* W    = (z == 0) ? W0 : (z == 1 ? W1 : W2);
    const float* bias = (z == 0) ? b0 : (z == 1 ? b1 : b2);
    float* C = g_proj + (size_t)z * GM * GN;

    const int m0 = blockIdx.y * BM;
    const int n0 = blockIdx.x * BN;
    const int tid = threadIdx.x;

    // global->smem staging assignments
    const int a_row = tid >> 1;
    const int a_k   = (tid & 1) * 4;
    const int b_row = tid >> 5;
    const int b_col = (tid & 31) * 4;

    // compute-tile mapping: 8 warps as 4x2, lanes as 4x8, 8x8 per thread
    const int warp = tid >> 5;
    const int lane = tid & 31;
    const int row0 = (warp & 3) * 32 + (lane & 3) * 8;
    const int col0 = (warp >> 2) * 64 + (lane >> 2) * 8;

    unsigned long long acc[8][4];
#pragma unroll
    for (int i = 0; i < 8; i++)
#pragma unroll
        for (int j = 0; j < 4; j++) acc[i][j] = 0ull;

    const float* Aptr = A + (size_t)(m0 + a_row) * GK + a_k;
    const float* Wptr = W + (size_t)b_row * GN + n0 + b_col;

    float4 ra = *(const float4*)Aptr;
    float4 rb = *(const float4*)Wptr;

    const int KT = GK / BKK;
    for (int kt = 0; kt < KT; kt++) {
        As[a_k + 0][a_row] = ra.x;
        As[a_k + 1][a_row] = ra.y;
        As[a_k + 2][a_row] = ra.z;
        As[a_k + 3][a_row] = ra.w;
        *(float4*)&Bs[b_row][b_col] = rb;
        __syncthreads();

        if (kt + 1 < KT) {
            ra = *(const float4*)(Aptr + (kt + 1) * BKK);
            rb = *(const float4*)(Wptr + (size_t)(kt + 1) * BKK * GN);
        }

#pragma unroll
        for (int k = 0; k < BKK; k++) {
            float4 a0 = *(const float4*)&As[k][row0];
            float4 a1 = *(const float4*)&As[k][row0 + 4];
            ulonglong2 bq0 = *(const ulonglong2*)&Bs[k][col0];
            ulonglong2 bq1 = *(const ulonglong2*)&Bs[k][col0 + 4];
            unsigned long long av[8];
            av[0] = pack2(a0.x, a0.x); av[1] = pack2(a0.y, a0.y);
            av[2] = pack2(a0.z, a0.z); av[3] = pack2(a0.w, a0.w);
            av[4] = pack2(a1.x, a1.x); av[5] = pack2(a1.y, a1.y);
            av[6] = pack2(a1.z, a1.z); av[7] = pack2(a1.w, a1.w);
#pragma unroll
            for (int i = 0; i < 8; i++) {
                fma2(acc[i][0], av[i], bq0.x);
                fma2(acc[i][1], av[i], bq0.y);
                fma2(acc[i][2], av[i], bq1.x);
                fma2(acc[i][3], av[i], bq1.y);
            }
        }
        __syncthreads();
    }

    float bb[8];
#pragma unroll
    for (int j = 0; j < 8; j++) bb[j] = bias[n0 + col0 + j];

#pragma unroll
    for (int i = 0; i < 8; i++) {
        float o[8];
#pragma unroll
        for (int jp = 0; jp < 4; jp++) {
            float2 v = unpack2(acc[i][jp]);
            o[2 * jp]     = v.x + bb[2 * jp];
            o[2 * jp + 1] = v.y + bb[2 * jp + 1];
        }
        size_t base = (size_t)(m0 + row0 + i) * GN + n0 + col0;
        *(float4*)&C[base]     = make_float4(o[0], o[1], o[2], o[3]);
        *(float4*)&C[base + 4] = make_float4(o[4], o[5], o[6], o[7]);
    }
}

// ---------------------------------------------------------------------------
// Scan: one CTA (512 threads) per batch element. h lives in SMEM. Block 0's
// three 128x128 matrices (192 KB) are cached in SMEM (block 0 is active every
// step). Blocks 1-3 stream from L2 only on their active steps.
// Per step:
//   phase1: r_i = sigmoid(xrt[:, :m] + h[:m] @ Cr_i); rh_i = r_i * h[:m]
//   phase2: z   = sigmoid(xzt[:, iN:] + h[:m] @ Cz_i)
//           hn  = sigmoid(xt [:, iN:] + rh_i @ Ch_i)
//           v   = z*hn + (1-z)*h[iN:]   -> h[iN:] = v  (active blocks only)
//   out[b, t, :] = h
// ---------------------------------------------------------------------------
__global__ void __launch_bounds__(512) scan_kernel(
    const float* __restrict__ ch0, const float* __restrict__ cr0, const float* __restrict__ cz0,
    const float* __restrict__ ch1, const float* __restrict__ cr1, const float* __restrict__ cz1,
    const float* __restrict__ ch2, const float* __restrict__ cr2, const float* __restrict__ cz2,
    const float* __restrict__ ch3, const float* __restrict__ cr3, const float* __restrict__ cz3,
    float* __restrict__ out)
{
    extern __shared__ float smem[];
    float* h_s   = smem;            // 512
    float* rh_s  = smem + 512;      // 1280 (block offsets 0,128,384,768)
    float* cr0_s = smem + 1792;     // 16384
    float* cz0_s = cr0_s + 16384;   // 16384
    float* ch0_s = cz0_s + 16384;   // 16384

    const int b   = blockIdx.x;
    const int tid = threadIdx.x;

    // preload block-0 matrices into SMEM (float4, fully coalesced)
    {
        const float4* s1 = (const float4*)cr0; float4* d1 = (float4*)cr0_s;
        const float4* s2 = (const float4*)cz0; float4* d2 = (float4*)cz0_s;
        const float4* s3 = (const float4*)ch0; float4* d3 = (float4*)ch0_s;
        for (int i = tid; i < 4096; i += 512) {
            d1[i] = s1[i]; d2[i] = s2[i]; d3[i] = s3[i];
        }
    }
    h_s[tid] = 0.0f;
    __syncthreads();

    const float* xt  = g_proj;
    const float* xrt = g_proj + (size_t)GM * GN;
    const float* xzt = g_proj + 2ull * GM * GN;

    const float* CR[4] = {cr0, cr1, cr2, cr3};
    const float* CZ[4] = {cz0, cz1, cz2, cz3};
    const float* CH[4] = {ch0, ch1, ch2, ch3};
    const int Ms[4]  = {128, 256, 384, 512};
    const int OFF[4] = {0, 128, 384, 768};

    for (int t = 0; t < SEQ_LEN; t++) {
        int act[4]; int na = 0;
        act[na++] = 0;
        if ((t & 1) == 0) act[na++] = 1;
        if ((t & 3) == 0) act[na++] = 2;
        if ((t & 7) == 0) act[na++] = 3;

        const size_t xrow = ((size_t)b * SEQ_LEN + t) * GN;

        // ---- phase 1: r and rh for all active blocks (pair-vectorized) ----
        int pbase[4]; int P = 0;
        for (int a = 0; a < na; a++) { pbase[a] = P; P += Ms[act[a]] >> 1; }

        for (int s = tid; s < P; s += 512) {
            int a = 0;
            while (a + 1 < na && s >= pbase[a + 1]) a++;
            const int i  = act[a];
            const int j0 = (s - pbase[a]) * 2;
            const int m  = Ms[i];
            float ax = 0.f, ay = 0.f;
            if (i == 0) {
#pragma unroll 8
                for (int k = 0; k < 128; k++) {
                    float hk = h_s[k];
                    float2 w = *(const float2*)&cr0_s[(k << 7) + j0];
                    ax += hk * w.x; ay += hk * w.y;
                }
            } else {
                const float* crp = CR[i] + j0;
#pragma unroll 8
                for (int k = 0; k < m; k++) {
                    float hk = h_s[k];
                    float2 w = *(const float2*)&crp[k * m];
                    ax += hk * w.x; ay += hk * w.y;
                }
            }
            float rx = sigmoidf_(xrt[xrow + j0]     + ax);
            float ry = sigmoidf_(xrt[xrow + j0 + 1] + ay);
            rh_s[OFF[i] + j0]     = rx * h_s[j0];
            rh_s[OFF[i] + j0 + 1] = ry * h_s[j0 + 1];
        }
        __syncthreads();

        // ---- phase 2: z, h_new, v (<=256 pair-slots, one per thread) ----
        float vx = 0.f, vy = 0.f; int col = 0;
        const int P2 = na << 6;   // 64 pairs per active block
        if (tid < P2) {
            const int i   = act[tid >> 6];
            const int j0  = (tid & 63) * 2;
            const int m   = Ms[i];
            const int off = OFF[i];
            float azx = 0.f, azy = 0.f, ahx = 0.f, ahy = 0.f;
            if (i == 0) {
#pragma unroll 8
                for (int k = 0; k < 128; k++) {
                    float hk = h_s[k], rk = rh_s[k];
                    float2 wz = *(const float2*)&cz0_s[(k << 7) + j0];
                    float2 wh = *(const float2*)&ch0_s[(k << 7) + j0];
                    azx += hk * wz.x; azy += hk * wz.y;
                    ahx += rk * wh.x; ahy += rk * wh.y;
                }
            } else {
                const float* czp = CZ[i] + j0;
                const float* chp = CH[i] + j0;
#pragma unroll 8
                for (int k = 0; k < m; k++) {
                    float hk = h_s[k], rk = rh_s[off + k];
                    float2 wz = *(const float2*)&czp[k << 7];
                    float2 wh = *(const float2*)&chp[k << 7];
                    azx += hk * wz.x; azy += hk * wz.y;
                    ahx += rk * wh.x; ahy += rk * wh.y;
                }
            }
            col = (i << 7) + j0;
            float zx  = sigmoidf_(xzt[xrow + col]     + azx);
            float zy  = sigmoidf_(xzt[xrow + col + 1] + azy);
            float hnx = sigmoidf_(xt [xrow + col]     + ahx);
            float hny = sigmoidf_(xt [xrow + col + 1] + ahy);
            vx = zx * hnx + (1.0f - zx) * h_s[col];
            vy = zy * hny + (1.0f - zy) * h_s[col + 1];
        }
        __syncthreads();   // all reads of old h complete
        if (tid < P2) { h_s[col] = vx; h_s[col + 1] = vy; }
        __syncthreads();   // h updated

        out[xrow + tid] = h_s[tid];
    }
}

// ---------------------------------------------------------------------------
extern "C" void kernel_launch(void* const* d_in, const int* in_sizes, int n_in,
                              void* d_out, int out_size) {
    (void)in_sizes; (void)n_in; (void)out_size;
    const float* x  = (const float*)d_in[0];
    const float* W  = (const float*)d_in[1];
    const float* bb = (const float*)d_in[2];
    const float* Wr = (const float*)d_in[3];
    const float* br = (const float*)d_in[4];
    const float* Wz = (const float*)d_in[5];
    const float* bz = (const float*)d_in[6];
    const float* ch[4]; const float* cr[4]; const float* cz[4];
    for (int i = 0; i < 4; i++) {
        ch[i] = (const float*)d_in[7 + 3 * i + 0];
        cr[i] = (const float*)d_in[7 + 3 * i + 1];
        cz[i] = (const float*)d_in[7 + 3 * i + 2];
    }
    float* out = (float*)d_out;

    // Phase A: the three projections (ordered before scan on same stream)
    dim3 grid(GN / BN, GM / BM, 3);
    gemm3_kernel<<<grid, 256>>>(x, W, bb, Wr, br, Wz, bz);

    // Phase B: scan, one CTA per batch element
    size_t smem_bytes = (512 + 1280 + 3 * 16384) * sizeof(float); // 203776 B
    cudaFuncSetAttribute(scan_kernel,
                         cudaFuncAttributeMaxDynamicSharedMemorySize,
                         (int)smem_bytes);
    scan_kernel<<<NBATCH, 512, smem_bytes>>>(
        ch[0], cr[0], cz[0],
        ch[1], cr[1], cz[1],
        ch[2], cr[2], cz[2],
        ch[3], cr[3], cz[3],
        out);
}

// round 3
// speedup vs baseline: 2.5567x; 2.5567x over previous
#include <cuda_runtime.h>

// ---------------------------------------------------------------------------
// ClockworkGRU:
//   Phase A: proj[z] = x @ Wz + bz for z in {W, Wr, Wz}   (3x SGEMM, fp32)
//   Phase B: sequential scan, one CTA per batch element.
// ---------------------------------------------------------------------------

#define GM 32768   // B*SEQ rows
#define GK 512
#define GN 512
#define SEQ_LEN 512
#define NBATCH 64

__device__ float g_proj[3ull * GM * GN];

// ---------------- packed f32x2 helpers (GEMM) --------------------------------
__device__ __forceinline__ unsigned long long pack2(float x, float y) {
    unsigned long long r;
    asm("mov.b64 %0, {%1, %2};" : "=l"(r) : "f"(x), "f"(y));
    return r;
}
__device__ __forceinline__ void fma2(unsigned long long& d,
                                     unsigned long long a,
                                     unsigned long long b) {
    asm("fma.rn.f32x2 %0, %1, %2, %0;" : "+l"(d) : "l"(a), "l"(b));
}
__device__ __forceinline__ float2 unpack2(unsigned long long v) {
    float2 r;
    asm("mov.b64 {%0, %1}, %2;" : "=f"(r.x), "=f"(r.y) : "l"(v));
    return r;
}

__device__ __forceinline__ float sigmoidf_(float x) {
    return 1.0f / (1.0f + __expf(-x));
}

// ---------------------------------------------------------------------------
// GEMM (unchanged from R2 — measured ~0.9 ms, not the bottleneck)
// ---------------------------------------------------------------------------
#define BM 128
#define BN 128
#define BKK 8

__global__ void __launch_bounds__(256) gemm3_kernel(
    const float* __restrict__ A,
    const float* __restrict__ W0, const float* __restrict__ b0,
    const float* __restrict__ W1, const float* __restrict__ b1,
    const float* __restrict__ W2, const float* __restrict__ b2)
{
    __shared__ float As[BKK][BM];
    __shared__ float Bs[BKK][BN];

    const int z = blockIdx.z;
    const float* W    = (z == 0) ? W0 : (z == 1 ? W1 : W2);
    const float* bias = (z == 0) ? b0 : (z == 1 ? b1 : b2);
    float* C = g_proj + (size_t)z * GM * GN;

    const int m0 = blockIdx.y * BM;
    const int n0 = blockIdx.x * BN;
    const int tid = threadIdx.x;

    const int a_row = tid >> 1;
    const int a_k   = (tid & 1) * 4;
    const int b_row = tid >> 5;
    const int b_col = (tid & 31) * 4;

    const int warp = tid >> 5;
    const int lane = tid & 31;
    const int row0 = (warp & 3) * 32 + (lane & 3) * 8;
    const int col0 = (warp >> 2) * 64 + (lane >> 2) * 8;

    unsigned long long acc[8][4];
#pragma unroll
    for (int i = 0; i < 8; i++)
#pragma unroll
        for (int j = 0; j < 4; j++) acc[i][j] = 0ull;

    const float* Aptr = A + (size_t)(m0 + a_row) * GK + a_k;
    const float* Wptr = W + (size_t)b_row * GN + n0 + b_col;

    float4 ra = *(const float4*)Aptr;
    float4 rb = *(const float4*)Wptr;

    const int KT = GK / BKK;
    for (int kt = 0; kt < KT; kt++) {
        As[a_k + 0][a_row] = ra.x;
        As[a_k + 1][a_row] = ra.y;
        As[a_k + 2][a_row] = ra.z;
        As[a_k + 3][a_row] = ra.w;
        *(float4*)&Bs[b_row][b_col] = rb;
        __syncthreads();

        if (kt + 1 < KT) {
            ra = *(const float4*)(Aptr + (kt + 1) * BKK);
            rb = *(const float4*)(Wptr + (size_t)(kt + 1) * BKK * GN);
        }

#pragma unroll
        for (int k = 0; k < BKK; k++) {
            float4 a0 = *(const float4*)&As[k][row0];
            float4 a1 = *(const float4*)&As[k][row0 + 4];
            ulonglong2 bq0 = *(const ulonglong2*)&Bs[k][col0];
            ulonglong2 bq1 = *(const ulonglong2*)&Bs[k][col0 + 4];
            unsigned long long av[8];
            av[0] = pack2(a0.x, a0.x); av[1] = pack2(a0.y, a0.y);
            av[2] = pack2(a0.z, a0.z); av[3] = pack2(a0.w, a0.w);
            av[4] = pack2(a1.x, a1.x); av[5] = pack2(a1.y, a1.y);
            av[6] = pack2(a1.z, a1.z); av[7] = pack2(a1.w, a1.w);
#pragma unroll
            for (int i = 0; i < 8; i++) {
                fma2(acc[i][0], av[i], bq0.x);
                fma2(acc[i][1], av[i], bq0.y);
                fma2(acc[i][2], av[i], bq1.x);
                fma2(acc[i][3], av[i], bq1.y);
            }
        }
        __syncthreads();
    }

    float bb[8];
#pragma unroll
    for (int j = 0; j < 8; j++) bb[j] = bias[n0 + col0 + j];

#pragma unroll
    for (int i = 0; i < 8; i++) {
        float o[8];
#pragma unroll
        for (int jp = 0; jp < 4; jp++) {
            float2 v = unpack2(acc[i][jp]);
            o[2 * jp]     = v.x + bb[2 * jp];
            o[2 * jp + 1] = v.y + bb[2 * jp + 1];
        }
        size_t base = (size_t)(m0 + row0 + i) * GN + n0 + col0;
        *(float4*)&C[base]     = make_float4(o[0], o[1], o[2], o[3]);
        *(float4*)&C[base + 4] = make_float4(o[4], o[5], o[6], o[7]);
    }
}

// ---------------------------------------------------------------------------
// Scan v2 — latency fix: all streaming dots use explicit 16-deep register
// batches of independent LDG.64 (guaranteed MLP=16 per thread; 16 warps/CTA
// then saturate the ~128 B/cyc L1tex wavefront service).
// ---------------------------------------------------------------------------

// dot over k<M of hv[k] * w[k*stride .. +1], global w, batched loads
__device__ __forceinline__ float2 dot_g(const float* __restrict__ w, int stride,
                                        int M, const float* __restrict__ hv)
{
    float ax = 0.f, ay = 0.f;
    for (int kb = 0; kb < M; kb += 16) {
        float2 wb[16];
        const float* wp = w + (size_t)kb * stride;
#pragma unroll
        for (int u = 0; u < 16; u++)
            wb[u] = *(const float2*)(wp + (size_t)u * stride);
#pragma unroll
        for (int u = 0; u < 16; u++) {
            float hk = hv[kb + u];
            ax = fmaf(hk, wb[u].x, ax);
            ay = fmaf(hk, wb[u].y, ay);
        }
    }
    return make_float2(ax, ay);
}

// dot over k<128 with SMEM-resident w (stride 128 floats)
__device__ __forceinline__ float2 dot_s128(const float* __restrict__ w,
                                           const float* __restrict__ hv)
{
    float ax = 0.f, ay = 0.f;
#pragma unroll 16
    for (int k = 0; k < 128; k++) {
        float hk = hv[k];
        float2 ww = *(const float2*)&w[k << 7];
        ax = fmaf(hk, ww.x, ax);
        ay = fmaf(hk, ww.y, ay);
    }
    return make_float2(ax, ay);
}

__global__ void __launch_bounds__(512) scan_kernel(
    const float* __restrict__ ch0, const float* __restrict__ cr0, const float* __restrict__ cz0,
    const float* __restrict__ ch1, const float* __restrict__ cr1, const float* __restrict__ cz1,
    const float* __restrict__ ch2, const float* __restrict__ cr2, const float* __restrict__ cz2,
    const float* __restrict__ ch3, const float* __restrict__ cr3, const float* __restrict__ cz3,
    float* __restrict__ out)
{
    extern __shared__ float smem[];
    float* h_s   = smem;              // 512
    float* rh_s  = smem + 512;        // 1280 (block offsets 0,128,384,768)
    float* zb_s  = smem + 1792;       // 512
    float* hn_s  = smem + 2304;       // 512
    float* cr0_s = smem + 2816;       // 16384
    float* cz0_s = cr0_s + 16384;     // 16384
    float* ch0_s = cz0_s + 16384;     // 16384

    const int b   = blockIdx.x;
    const int tid = threadIdx.x;

    // preload block-0 matrices (192 KB) into SMEM
    {
        const float4* s1 = (const float4*)cr0; float4* d1 = (float4*)cr0_s;
        const float4* s2 = (const float4*)cz0; float4* d2 = (float4*)cz0_s;
        const float4* s3 = (const float4*)ch0; float4* d3 = (float4*)ch0_s;
        for (int i = tid; i < 4096; i += 512) {
            d1[i] = s1[i]; d2[i] = s2[i]; d3[i] = s3[i];
        }
    }
    h_s[tid] = 0.0f;
    __syncthreads();

    const float* xt  = g_proj;
    const float* xrt = g_proj + (size_t)GM * GN;
    const float* xzt = g_proj + 2ull * GM * GN;

    const float* CR[4] = {cr0, cr1, cr2, cr3};
    const float* CZ[4] = {cz0, cz1, cz2, cz3};
    const float* CH[4] = {ch0, ch1, ch2, ch3};
    const int Ms[4]  = {128, 256, 384, 512};
    const int OFF[4] = {0, 128, 384, 768};

    for (int t = 0; t < SEQ_LEN; t++) {
        int act[4]; int na = 0;
        act[na++] = 0;
        if ((t & 1) == 0) act[na++] = 1;
        if ((t & 3) == 0) act[na++] = 2;
        if ((t & 7) == 0) act[na++] = 3;

        const size_t xrow = ((size_t)b * SEQ_LEN + t) * GN;

        // ---- phase A: r_i and rh_i for all active blocks (pair columns) ----
        int pbase[4]; int P = 0;
        for (int a = 0; a < na; a++) { pbase[a] = P; P += Ms[act[a]] >> 1; }

        for (int s = tid; s < P; s += 512) {
            int a = 0;
            while (a + 1 < na && s >= pbase[a + 1]) a++;
            const int i  = act[a];
            const int j0 = (s - pbase[a]) * 2;
            float2 acc;
            if (i == 0) acc = dot_s128(cr0_s + j0, h_s);
            else        acc = dot_g(CR[i] + j0, Ms[i], Ms[i], h_s);
            float rx = sigmoidf_(xrt[xrow + j0]     + acc.x);
            float ry = sigmoidf_(xrt[xrow + j0 + 1] + acc.y);
            rh_s[OFF[i] + j0]     = rx * h_s[j0];
            rh_s[OFF[i] + j0 + 1] = ry * h_s[j0 + 1];
        }
        __syncthreads();

        // ---- phase B: z and h_new dots as independent tasks --------------
        // 128 tasks per active block: 64 z-pairs then 64 hn-pairs
        const int T2 = na << 7;
        if (tid < T2) {
            const int a    = tid >> 7;
            const int i    = act[a];
            const int r    = tid & 127;
            const int kind = r >> 6;            // 0 = z, 1 = h_new
            const int j0   = (r & 63) * 2;
            const int m    = Ms[i];
            const int col  = (i << 7) + j0;
            if (kind == 0) {
                float2 acc = (i == 0) ? dot_s128(cz0_s + j0, h_s)
                                      : dot_g(CZ[i] + j0, 128, m, h_s);
                zb_s[col]     = sigmoidf_(xzt[xrow + col]     + acc.x);
                zb_s[col + 1] = sigmoidf_(xzt[xrow + col + 1] + acc.y);
            } else {
                const float* rhv = rh_s + OFF[i];
                float2 acc = (i == 0) ? dot_s128(ch0_s + j0, rhv)
                                      : dot_g(CH[i] + j0, 128, m, rhv);
                hn_s[col]     = sigmoidf_(xt[xrow + col]     + acc.x);
                hn_s[col + 1] = sigmoidf_(xt[xrow + col + 1] + acc.y);
            }
        }
        __syncthreads();

        // ---- phase C: gate combine + h update -----------------------------
        const int T3 = na << 6;
        if (tid < T3) {
            const int i   = act[tid >> 6];
            const int j0  = (tid & 63) * 2;
            const int col = (i << 7) + j0;
            float zx = zb_s[col],     zy = zb_s[col + 1];
            float vx = zx * hn_s[col]     + (1.0f - zx) * h_s[col];
            float vy = zy * hn_s[col + 1] + (1.0f - zy) * h_s[col + 1];
            h_s[col]     = vx;
            h_s[col + 1] = vy;
        }
        __syncthreads();

        out[xrow + tid] = h_s[tid];
    }
}

// ---------------------------------------------------------------------------
extern "C" void kernel_launch(void* const* d_in, const int* in_sizes, int n_in,
                              void* d_out, int out_size) {
    (void)in_sizes; (void)n_in; (void)out_size;
    const float* x  = (const float*)d_in[0];
    const float* W  = (const float*)d_in[1];
    const float* bb = (const float*)d_in[2];
    const float* Wr = (const float*)d_in[3];
    const float* br = (const float*)d_in[4];
    const float* Wz = (const float*)d_in[5];
    const float* bz = (const float*)d_in[6];
    const float* ch[4]; const float* cr[4]; const float* cz[4];
    for (int i = 0; i < 4; i++) {
        ch[i] = (const float*)d_in[7 + 3 * i + 0];
        cr[i] = (const float*)d_in[7 + 3 * i + 1];
        cz[i] = (const float*)d_in[7 + 3 * i + 2];
    }
    float* out = (float*)d_out;

    dim3 grid(GN / BN, GM / BM, 3);
    gemm3_kernel<<<grid, 256>>>(x, W, bb, Wr, br, Wz, bz);

    size_t smem_bytes = (2816 + 3 * 16384) * sizeof(float); // 207,872 B
    cudaFuncSetAttribute(scan_kernel,
                         cudaFuncAttributeMaxDynamicSharedMemorySize,
                         (int)smem_bytes);
    scan_kernel<<<NBATCH, 512, smem_bytes>>>(
        ch[0], cr[0], cz[0],
        ch[1], cr[1], cz[1],
        ch[2], cr[2], cz[2],
        ch[3], cr[3], cz[3],
        out);
}

// round 4
// speedup vs baseline: 4.4958x; 1.7585x over previous
#include <cuda_runtime.h>

// ---------------------------------------------------------------------------
// ClockworkGRU:
//   Phase A: proj[z] = x @ Wz + bz for z in {W, Wr, Wz}   (3x SGEMM, fp32)
//   Phase B: sequential scan, one CTA per batch element.
// ---------------------------------------------------------------------------

#define GM 32768   // B*SEQ rows
#define GK 512
#define GN 512
#define SEQ_LEN 512
#define NBATCH 64

__device__ float g_proj[3ull * GM * GN];

// ---------------- packed f32x2 helpers (GEMM) --------------------------------
__device__ __forceinline__ unsigned long long pack2(float x, float y) {
    unsigned long long r;
    asm("mov.b64 %0, {%1, %2};" : "=l"(r) : "f"(x), "f"(y));
    return r;
}
__device__ __forceinline__ void fma2(unsigned long long& d,
                                     unsigned long long a,
                                     unsigned long long b) {
    asm("fma.rn.f32x2 %0, %1, %2, %0;" : "+l"(d) : "l"(a), "l"(b));
}
__device__ __forceinline__ float2 unpack2(unsigned long long v) {
    float2 r;
    asm("mov.b64 {%0, %1}, %2;" : "=f"(r.x), "=f"(r.y) : "l"(v));
    return r;
}

__device__ __forceinline__ float sigmoidf_(float x) {
    return 1.0f / (1.0f + __expf(-x));
}

// ---------------------------------------------------------------------------
// GEMM (unchanged — measured ~0.9 ms, not the current bottleneck)
// ---------------------------------------------------------------------------
#define BM 128
#define BN 128
#define BKK 8

__global__ void __launch_bounds__(256) gemm3_kernel(
    const float* __restrict__ A,
    const float* __restrict__ W0, const float* __restrict__ b0,
    const float* __restrict__ W1, const float* __restrict__ b1,
    const float* __restrict__ W2, const float* __restrict__ b2)
{
    __shared__ float As[BKK][BM];
    __shared__ float Bs[BKK][BN];

    const int z = blockIdx.z;
    const float* W    = (z == 0) ? W0 : (z == 1 ? W1 : W2);
    const float* bias = (z == 0) ? b0 : (z == 1 ? b1 : b2);
    float* C = g_proj + (size_t)z * GM * GN;

    const int m0 = blockIdx.y * BM;
    const int n0 = blockIdx.x * BN;
    const int tid = threadIdx.x;

    const int a_row = tid >> 1;
    const int a_k   = (tid & 1) * 4;
    const int b_row = tid >> 5;
    const int b_col = (tid & 31) * 4;

    const int warp = tid >> 5;
    const int lane = tid & 31;
    const int row0 = (warp & 3) * 32 + (lane & 3) * 8;
    const int col0 = (warp >> 2) * 64 + (lane >> 2) * 8;

    unsigned long long acc[8][4];
#pragma unroll
    for (int i = 0; i < 8; i++)
#pragma unroll
        for (int j = 0; j < 4; j++) acc[i][j] = 0ull;

    const float* Aptr = A + (size_t)(m0 + a_row) * GK + a_k;
    const float* Wptr = W + (size_t)b_row * GN + n0 + b_col;

    float4 ra = *(const float4*)Aptr;
    float4 rb = *(const float4*)Wptr;

    const int KT = GK / BKK;
    for (int kt = 0; kt < KT; kt++) {
        As[a_k + 0][a_row] = ra.x;
        As[a_k + 1][a_row] = ra.y;
        As[a_k + 2][a_row] = ra.z;
        As[a_k + 3][a_row] = ra.w;
        *(float4*)&Bs[b_row][b_col] = rb;
        __syncthreads();

        if (kt + 1 < KT) {
            ra = *(const float4*)(Aptr + (kt + 1) * BKK);
            rb = *(const float4*)(Wptr + (size_t)(kt + 1) * BKK * GN);
        }

#pragma unroll
        for (int k = 0; k < BKK; k++) {
            float4 a0 = *(const float4*)&As[k][row0];
            float4 a1 = *(const float4*)&As[k][row0 + 4];
            ulonglong2 bq0 = *(const ulonglong2*)&Bs[k][col0];
            ulonglong2 bq1 = *(const ulonglong2*)&Bs[k][col0 + 4];
            unsigned long long av[8];
            av[0] = pack2(a0.x, a0.x); av[1] = pack2(a0.y, a0.y);
            av[2] = pack2(a0.z, a0.z); av[3] = pack2(a0.w, a0.w);
            av[4] = pack2(a1.x, a1.x); av[5] = pack2(a1.y, a1.y);
            av[6] = pack2(a1.z, a1.z); av[7] = pack2(a1.w, a1.w);
#pragma unroll
            for (int i = 0; i < 8; i++) {
                fma2(acc[i][0], av[i], bq0.x);
                fma2(acc[i][1], av[i], bq0.y);
                fma2(acc[i][2], av[i], bq1.x);
                fma2(acc[i][3], av[i], bq1.y);
            }
        }
        __syncthreads();
    }

    float bb[8];
#pragma unroll
    for (int j = 0; j < 8; j++) bb[j] = bias[n0 + col0 + j];

#pragma unroll
    for (int i = 0; i < 8; i++) {
        float o[8];
#pragma unroll
        for (int jp = 0; jp < 4; jp++) {
            float2 v = unpack2(acc[i][jp]);
            o[2 * jp]     = v.x + bb[2 * jp];
            o[2 * jp + 1] = v.y + bb[2 * jp + 1];
        }
        size_t base = (size_t)(m0 + row0 + i) * GN + n0 + col0;
        *(float4*)&C[base]     = make_float4(o[0], o[1], o[2], o[3]);
        *(float4*)&C[base + 4] = make_float4(o[4], o[5], o[6], o[7]);
    }
}

// ---------------------------------------------------------------------------
// Scan v3 — 4 columns per thread via LDG.128, 16-deep register batches
// (64 regs of buffer, enabled by __launch_bounds__(512, 1) -> 128-reg budget).
// ---------------------------------------------------------------------------

// 4-column dot over k<M: acc[c] = sum_k hv[k] * w[k*stride + c], c=0..3
__device__ __forceinline__ float4 dot_g4(const float* __restrict__ w, int stride,
                                         int M, const float* __restrict__ hv)
{
    float a0 = 0.f, a1 = 0.f, a2 = 0.f, a3 = 0.f;
    for (int kb = 0; kb < M; kb += 16) {
        float4 wb[16];
        const float* wp = w + (size_t)kb * stride;
#pragma unroll
        for (int u = 0; u < 16; u++)
            wb[u] = *(const float4*)(wp + (size_t)u * stride);
        float4 h0 = *(const float4*)(hv + kb);
        float4 h1 = *(const float4*)(hv + kb + 4);
        float4 h2 = *(const float4*)(hv + kb + 8);
        float4 h3 = *(const float4*)(hv + kb + 12);
        float hk[16];
        hk[0]=h0.x; hk[1]=h0.y; hk[2]=h0.z; hk[3]=h0.w;
        hk[4]=h1.x; hk[5]=h1.y; hk[6]=h1.z; hk[7]=h1.w;
        hk[8]=h2.x; hk[9]=h2.y; hk[10]=h2.z; hk[11]=h2.w;
        hk[12]=h3.x; hk[13]=h3.y; hk[14]=h3.z; hk[15]=h3.w;
#pragma unroll
        for (int u = 0; u < 16; u++) {
            a0 = fmaf(hk[u], wb[u].x, a0);
            a1 = fmaf(hk[u], wb[u].y, a1);
            a2 = fmaf(hk[u], wb[u].z, a2);
            a3 = fmaf(hk[u], wb[u].w, a3);
        }
    }
    return make_float4(a0, a1, a2, a3);
}

// 4-column dot, k<128, SMEM-resident w (row stride 128 floats)
__device__ __forceinline__ float4 dot_s4(const float* __restrict__ w,
                                         const float* __restrict__ hv)
{
    float a0 = 0.f, a1 = 0.f, a2 = 0.f, a3 = 0.f;
#pragma unroll 16
    for (int k = 0; k < 128; k++) {
        float hk = hv[k];
        float4 ww = *(const float4*)&w[k << 7];
        a0 = fmaf(hk, ww.x, a0);
        a1 = fmaf(hk, ww.y, a1);
        a2 = fmaf(hk, ww.z, a2);
        a3 = fmaf(hk, ww.w, a3);
    }
    return make_float4(a0, a1, a2, a3);
}

__global__ void __launch_bounds__(512, 1) scan_kernel(
    const float* __restrict__ ch0, const float* __restrict__ cr0, const float* __restrict__ cz0,
    const float* __restrict__ ch1, const float* __restrict__ cr1, const float* __restrict__ cz1,
    const float* __restrict__ ch2, const float* __restrict__ cr2, const float* __restrict__ cz2,
    const float* __restrict__ ch3, const float* __restrict__ cr3, const float* __restrict__ cz3,
    float* __restrict__ out)
{
    extern __shared__ float smem[];
    float* h_s   = smem;              // 512
    float* rh_s  = smem + 512;        // 1280 (block offsets 0,128,384,768)
    float* zb_s  = smem + 1792;       // 512
    float* hn_s  = smem + 2304;       // 512
    float* cr0_s = smem + 2816;       // 16384
    float* cz0_s = cr0_s + 16384;     // 16384
    float* ch0_s = cz0_s + 16384;     // 16384

    const int b   = blockIdx.x;
    const int tid = threadIdx.x;

    // preload block-0 matrices (192 KB) into SMEM
    {
        const float4* s1 = (const float4*)cr0; float4* d1 = (float4*)cr0_s;
        const float4* s2 = (const float4*)cz0; float4* d2 = (float4*)cz0_s;
        const float4* s3 = (const float4*)ch0; float4* d3 = (float4*)ch0_s;
        for (int i = tid; i < 4096; i += 512) {
            d1[i] = s1[i]; d2[i] = s2[i]; d3[i] = s3[i];
        }
    }
    h_s[tid] = 0.0f;
    __syncthreads();

    const float* xt  = g_proj;
    const float* xrt = g_proj + (size_t)GM * GN;
    const float* xzt = g_proj + 2ull * GM * GN;

    const float* CR[4] = {cr0, cr1, cr2, cr3};
    const float* CZ[4] = {cz0, cz1, cz2, cz3};
    const float* CH[4] = {ch0, ch1, ch2, ch3};
    const int Ms[4]  = {128, 256, 384, 512};
    const int OFF[4] = {0, 128, 384, 768};

    for (int t = 0; t < SEQ_LEN; t++) {
        int act[4]; int na = 0;
        act[na++] = 0;
        if ((t & 1) == 0) act[na++] = 1;
        if ((t & 3) == 0) act[na++] = 2;
        if ((t & 7) == 0) act[na++] = 3;

        const size_t xrow = ((size_t)b * SEQ_LEN + t) * GN;

        // ---- phase A: r and rh for all active blocks (quad columns) -------
        int pbase[4]; int P = 0;
        for (int a = 0; a < na; a++) { pbase[a] = P; P += Ms[act[a]] >> 2; }

        for (int s = tid; s < P; s += 512) {
            int a = 0;
            while (a + 1 < na && s >= pbase[a + 1]) a++;
            const int i  = act[a];
            const int j0 = (s - pbase[a]) * 4;
            float4 acc;
            if (i == 0) acc = dot_s4(cr0_s + j0, h_s);
            else        acc = dot_g4(CR[i] + j0, Ms[i], Ms[i], h_s);
            float4 xr = *(const float4*)&xrt[xrow + j0];
            const int o = OFF[i] + j0;
            rh_s[o]     = sigmoidf_(xr.x + acc.x) * h_s[j0];
            rh_s[o + 1] = sigmoidf_(xr.y + acc.y) * h_s[j0 + 1];
            rh_s[o + 2] = sigmoidf_(xr.z + acc.z) * h_s[j0 + 2];
            rh_s[o + 3] = sigmoidf_(xr.w + acc.w) * h_s[j0 + 3];
        }
        __syncthreads();

        // ---- phase B: z-dots and hn-dots as independent quad tasks --------
        // per active block: 32 z-quads + 32 hn-quads
        const int T2 = na << 6;
        if (tid < T2) {
            const int a    = tid >> 6;
            const int i    = act[a];
            const int r    = tid & 63;
            const int kind = r >> 5;          // 0 = z, 1 = h_new
            const int j0   = (r & 31) * 4;
            const int m    = Ms[i];
            const int col  = (i << 7) + j0;
            if (kind == 0) {
                float4 acc = (i == 0) ? dot_s4(cz0_s + j0, h_s)
                                      : dot_g4(CZ[i] + j0, 128, m, h_s);
                float4 xz = *(const float4*)&xzt[xrow + col];
                zb_s[col]     = sigmoidf_(xz.x + acc.x);
                zb_s[col + 1] = sigmoidf_(xz.y + acc.y);
                zb_s[col + 2] = sigmoidf_(xz.z + acc.z);
                zb_s[col + 3] = sigmoidf_(xz.w + acc.w);
            } else {
                const float* rhv = rh_s + OFF[i];
                float4 acc = (i == 0) ? dot_s4(ch0_s + j0, rhv)
                                      : dot_g4(CH[i] + j0, 128, m, rhv);
                float4 xh = *(const float4*)&xt[xrow + col];
                hn_s[col]     = sigmoidf_(xh.x + acc.x);
                hn_s[col + 1] = sigmoidf_(xh.y + acc.y);
                hn_s[col + 2] = sigmoidf_(xh.z + acc.z);
                hn_s[col + 3] = sigmoidf_(xh.w + acc.w);
            }
        }
        __syncthreads();

        // ---- phase C: gate combine + h update -----------------------------
        const int T3 = na << 5;
        if (tid < T3) {
            const int i   = act[tid >> 5];
            const int j0  = (tid & 31) * 4;
            const int col = (i << 7) + j0;
#pragma unroll
            for (int u = 0; u < 4; u++) {
                float z = zb_s[col + u];
                h_s[col + u] = z * hn_s[col + u] + (1.0f - z) * h_s[col + u];
            }
        }
        __syncthreads();

        out[xrow + tid] = h_s[tid];
    }
}

// ---------------------------------------------------------------------------
extern "C" void kernel_launch(void* const* d_in, const int* in_sizes, int n_in,
                              void* d_out, int out_size) {
    (void)in_sizes; (void)n_in; (void)out_size;
    const float* x  = (const float*)d_in[0];
    const float* W  = (const float*)d_in[1];
    const float* bb = (const float*)d_in[2];
    const float* Wr = (const float*)d_in[3];
    const float* br = (const float*)d_in[4];
    const float* Wz = (const float*)d_in[5];
    const float* bz = (const float*)d_in[6];
    const float* ch[4]; const float* cr[4]; const float* cz[4];
    for (int i = 0; i < 4; i++) {
        ch[i] = (const float*)d_in[7 + 3 * i + 0];
        cr[i] = (const float*)d_in[7 + 3 * i + 1];
        cz[i] = (const float*)d_in[7 + 3 * i + 2];
    }
    float* out = (float*)d_out;

    dim3 grid(GN / BN, GM / BM, 3);
    gemm3_kernel<<<grid, 256>>>(x, W, bb, Wr, br, Wz, bz);

    size_t smem_bytes = (2816 + 3 * 16384) * sizeof(float); // 207,872 B
    cudaFuncSetAttribute(scan_kernel,
                         cudaFuncAttributeMaxDynamicSharedMemorySize,
                         (int)smem_bytes);
    scan_kernel<<<NBATCH, 512, smem_bytes>>>(
        ch[0], cr[0], cz[0],
        ch[1], cr[1], cz[1],
        ch[2], cr[2], cz[2],
        ch[3], cr[3], cz[3],
        out);
}

// round 5
// speedup vs baseline: 4.7707x; 1.0611x over previous
#include <cuda_runtime.h>

// ---------------------------------------------------------------------------
// ClockworkGRU:
//   Phase A: proj[z] = x @ Wz + bz for z in {W, Wr, Wz}   (3x SGEMM, fp32)
//   Phase B: sequential scan, one CTA per batch element.
// ---------------------------------------------------------------------------

#define GM 32768   // B*SEQ rows
#define GK 512
#define GN 512
#define SEQ_LEN 512
#define NBATCH 64

__device__ float g_proj[3ull * GM * GN];

// ---------------- packed f32x2 helpers (GEMM) --------------------------------
__device__ __forceinline__ unsigned long long pack2(float x, float y) {
    unsigned long long r;
    asm("mov.b64 %0, {%1, %2};" : "=l"(r) : "f"(x), "f"(y));
    return r;
}
__device__ __forceinline__ void fma2(unsigned long long& d,
                                     unsigned long long a,
                                     unsigned long long b) {
    asm("fma.rn.f32x2 %0, %1, %2, %0;" : "+l"(d) : "l"(a), "l"(b));
}
__device__ __forceinline__ float2 unpack2(unsigned long long v) {
    float2 r;
    asm("mov.b64 {%0, %1}, %2;" : "=f"(r.x), "=f"(r.y) : "l"(v));
    return r;
}

__device__ __forceinline__ float sigmoidf_(float x) {
    return 1.0f / (1.0f + __expf(-x));
}

// ---------------------------------------------------------------------------
// GEMM (unchanged — measured ~0.95 ms)
// ---------------------------------------------------------------------------
#define BM 128
#define BN 128
#define BKK 8

__global__ void __launch_bounds__(256) gemm3_kernel(
    const float* __restrict__ A,
    const float* __restrict__ W0, const float* __restrict__ b0,
    const float* __restrict__ W1, const float* __restrict__ b1,
    const float* __restrict__ W2, const float* __restrict__ b2)
{
    __shared__ float As[BKK][BM];
    __shared__ float Bs[BKK][BN];

    const int z = blockIdx.z;
    const float* W    = (z == 0) ? W0 : (z == 1 ? W1 : W2);
    const float* bias = (z == 0) ? b0 : (z == 1 ? b1 : b2);
    float* C = g_proj + (size_t)z * GM * GN;

    const int m0 = blockIdx.y * BM;
    const int n0 = blockIdx.x * BN;
    const int tid = threadIdx.x;

    const int a_row = tid >> 1;
    const int a_k   = (tid & 1) * 4;
    const int b_row = tid >> 5;
    const int b_col = (tid & 31) * 4;

    const int warp = tid >> 5;
    const int lane = tid & 31;
    const int row0 = (warp & 3) * 32 + (lane & 3) * 8;
    const int col0 = (warp >> 2) * 64 + (lane >> 2) * 8;

    unsigned long long acc[8][4];
#pragma unroll
    for (int i = 0; i < 8; i++)
#pragma unroll
        for (int j = 0; j < 4; j++) acc[i][j] = 0ull;

    const float* Aptr = A + (size_t)(m0 + a_row) * GK + a_k;
    const float* Wptr = W + (size_t)b_row * GN + n0 + b_col;

    float4 ra = *(const float4*)Aptr;
    float4 rb = *(const float4*)Wptr;

    const int KT = GK / BKK;
    for (int kt = 0; kt < KT; kt++) {
        As[a_k + 0][a_row] = ra.x;
        As[a_k + 1][a_row] = ra.y;
        As[a_k + 2][a_row] = ra.z;
        As[a_k + 3][a_row] = ra.w;
        *(float4*)&Bs[b_row][b_col] = rb;
        __syncthreads();

        if (kt + 1 < KT) {
            ra = *(const float4*)(Aptr + (kt + 1) * BKK);
            rb = *(const float4*)(Wptr + (size_t)(kt + 1) * BKK * GN);
        }

#pragma unroll
        for (int k = 0; k < BKK; k++) {
            float4 a0 = *(const float4*)&As[k][row0];
            float4 a1 = *(const float4*)&As[k][row0 + 4];
            ulonglong2 bq0 = *(const ulonglong2*)&Bs[k][col0];
            ulonglong2 bq1 = *(const ulonglong2*)&Bs[k][col0 + 4];
            unsigned long long av[8];
            av[0] = pack2(a0.x, a0.x); av[1] = pack2(a0.y, a0.y);
            av[2] = pack2(a0.z, a0.z); av[3] = pack2(a0.w, a0.w);
            av[4] = pack2(a1.x, a1.x); av[5] = pack2(a1.y, a1.y);
            av[6] = pack2(a1.z, a1.z); av[7] = pack2(a1.w, a1.w);
#pragma unroll
            for (int i = 0; i < 8; i++) {
                fma2(acc[i][0], av[i], bq0.x);
                fma2(acc[i][1], av[i], bq0.y);
                fma2(acc[i][2], av[i], bq1.x);
                fma2(acc[i][3], av[i], bq1.y);
            }
        }
        __syncthreads();
    }

    float bb[8];
#pragma unroll
    for (int j = 0; j < 8; j++) bb[j] = bias[n0 + col0 + j];

#pragma unroll
    for (int i = 0; i < 8; i++) {
        float o[8];
#pragma unroll
        for (int jp = 0; jp < 4; jp++) {
            float2 v = unpack2(acc[i][jp]);
            o[2 * jp]     = v.x + bb[2 * jp];
            o[2 * jp + 1] = v.y + bb[2 * jp + 1];
        }
        size_t base = (size_t)(m0 + row0 + i) * GN + n0 + col0;
        *(float4*)&C[base]     = make_float4(o[0], o[1], o[2], o[3]);
        *(float4*)&C[base + 4] = make_float4(o[4], o[5], o[6], o[7]);
    }
}

// ---------------------------------------------------------------------------
// Scan v4 — k-split tasks + software-pipelined (double-buffered) streaming
// dots + SMEM atomic accumulation. All 512 threads busy every pass.
// ---------------------------------------------------------------------------

// streaming 4-col dot over a 128-deep k segment, double-buffered 8+8
__device__ __forceinline__ void dot_g4db(const float* __restrict__ w, int stride,
                                         const float* __restrict__ hv,
                                         float acc[4])
{
    float4 A[8], B[8];
#pragma unroll
    for (int r = 0; r < 8; r++) A[r] = *(const float4*)(w + (size_t)r * stride);
    for (int kb = 0; kb < 128; kb += 16) {
#pragma unroll
        for (int r = 0; r < 8; r++)
            B[r] = *(const float4*)(w + (size_t)(kb + 8 + r) * stride);
#pragma unroll
        for (int r = 0; r < 8; r++) {
            float hk = hv[kb + r];
            acc[0] = fmaf(hk, A[r].x, acc[0]);
            acc[1] = fmaf(hk, A[r].y, acc[1]);
            acc[2] = fmaf(hk, A[r].z, acc[2]);
            acc[3] = fmaf(hk, A[r].w, acc[3]);
        }
        if (kb + 16 < 128) {
#pragma unroll
            for (int r = 0; r < 8; r++)
                A[r] = *(const float4*)(w + (size_t)(kb + 16 + r) * stride);
        }
#pragma unroll
        for (int r = 0; r < 8; r++) {
            float hk = hv[kb + 8 + r];
            acc[0] = fmaf(hk, B[r].x, acc[0]);
            acc[1] = fmaf(hk, B[r].y, acc[1]);
            acc[2] = fmaf(hk, B[r].z, acc[2]);
            acc[3] = fmaf(hk, B[r].w, acc[3]);
        }
    }
}

// SMEM 4-col dot over a 32-deep k segment (block 0, row stride 128 floats)
__device__ __forceinline__ float4 dot_s4_32(const float* __restrict__ w,
                                            const float* __restrict__ hv)
{
    float a0 = 0.f, a1 = 0.f, a2 = 0.f, a3 = 0.f;
#pragma unroll
    for (int k = 0; k < 32; k++) {
        float hk = hv[k];
        float4 ww = *(const float4*)&w[k << 7];
        a0 = fmaf(hk, ww.x, a0);
        a1 = fmaf(hk, ww.y, a1);
        a2 = fmaf(hk, ww.z, a2);
        a3 = fmaf(hk, ww.w, a3);
    }
    return make_float4(a0, a1, a2, a3);
}

__global__ void __launch_bounds__(512, 1) scan_kernel(
    const float* __restrict__ ch0, const float* __restrict__ cr0, const float* __restrict__ cz0,
    const float* __restrict__ ch1, const float* __restrict__ cr1, const float* __restrict__ cz1,
    const float* __restrict__ ch2, const float* __restrict__ cr2, const float* __restrict__ cz2,
    const float* __restrict__ ch3, const float* __restrict__ cr3, const float* __restrict__ cz3,
    float* __restrict__ out)
{
    extern __shared__ float smem[];
    float* h_s   = smem;              // 512
    float* rh_s  = smem + 512;        // 1280 (block offsets 0,128,384,768)
    float* racc  = smem + 1792;       // 1280
    float* zacc  = smem + 3072;       // 512
    float* hacc  = smem + 3584;       // 512
    float* cr0_s = smem + 4096;       // 16384
    float* cz0_s = cr0_s + 16384;     // 16384
    float* ch0_s = cz0_s + 16384;     // 16384

    const int b   = blockIdx.x;
    const int tid = threadIdx.x;

    // preload block-0 matrices (192 KB fp32) into SMEM
    {
        const float4* s1 = (const float4*)cr0; float4* d1 = (float4*)cr0_s;
        const float4* s2 = (const float4*)cz0; float4* d2 = (float4*)cz0_s;
        const float4* s3 = (const float4*)ch0; float4* d3 = (float4*)ch0_s;
        for (int i = tid; i < 4096; i += 512) {
            d1[i] = s1[i]; d2[i] = s2[i]; d3[i] = s3[i];
        }
    }
    h_s[tid] = 0.0f;
    __syncthreads();

    const float* xt  = g_proj;
    const float* xrt = g_proj + (size_t)GM * GN;
    const float* xzt = g_proj + 2ull * GM * GN;

    const float* CR[4] = {cr0, cr1, cr2, cr3};
    const float* CZ[4] = {cz0, cz1, cz2, cz3};
    const float* CH[4] = {ch0, ch1, ch2, ch3};
    const int OFF[4] = {0, 128, 384, 768};

    for (int t = 0; t < SEQ_LEN; t++) {
        int act[4]; int na = 0;
        act[na++] = 0;
        if ((t & 1) == 0) act[na++] = 1;
        if ((t & 3) == 0) act[na++] = 2;
        if ((t & 7) == 0) act[na++] = 3;

        int pb[5]; pb[0] = 0;
        for (int a = 0; a < na; a++) pb[a + 1] = pb[a] + ((act[a] + 1) << 7);
        const int LR = pb[na];

        const size_t xrow = ((size_t)b * SEQ_LEN + t) * GN;

        // ---- init accumulators with biases --------------------------------
        for (int s = tid; s < LR; s += 512) {
            int a = 0; while (a + 1 < na && s >= pb[a + 1]) a++;
            const int i = act[a], j = s - pb[a];
            racc[OFF[i] + j] = xrt[xrow + j];
        }
        for (int s = tid; s < (na << 7); s += 512) {
            const int i = act[s >> 7], j = s & 127, col = (i << 7) + j;
            zacc[col] = xzt[xrow + col];
            hacc[col] = xt[xrow + col];
        }
        __syncthreads();

        // ---- pass 1: r-dots and z-dots (k-split tasks) ---------------------
        // block 0 (SMEM): 128 r tasks + 128 z tasks (quad-col x 4 k-segs of 32)
        // block i>0: r = (m/4)*S quads, z = 32*S quads, k-segs of 128 (S=i+1)
        int total1 = 256;
        for (int a = 1; a < na; a++) {
            const int i = act[a], S = i + 1;
            total1 += (32 * (i + 1) + 32) * S;
        }
        for (int task = tid; task < total1; task += 512) {
            int tk = task;
            if (tk < 256) {
                const bool isZ = tk >= 128;
                const int idx  = tk & 127;
                const int q    = idx & 31, sgm = idx >> 5;
                const int col  = q * 4, k0 = sgm * 32;
                const float* w = (isZ ? cz0_s : cr0_s) + (k0 << 7) + col;
                float4 acc = dot_s4_32(w, h_s + k0);
                float* dst = isZ ? (zacc + col) : (racc + col);
                atomicAdd(dst + 0, acc.x);
                atomicAdd(dst + 1, acc.y);
                atomicAdd(dst + 2, acc.z);
                atomicAdd(dst + 3, acc.w);
            } else {
                tk -= 256;
                for (int a = 1; a < na; a++) {
                    const int i = act[a], S = i + 1, m = (i + 1) << 7;
                    const int rT = (m >> 2) * S;
                    if (tk < rT) {
                        const int q = tk % (m >> 2), sgm = tk / (m >> 2);
                        float acc[4] = {0.f, 0.f, 0.f, 0.f};
                        dot_g4db(CR[i] + (size_t)(sgm * 128) * m + q * 4, m,
                                 h_s + sgm * 128, acc);
                        float* dst = racc + OFF[i] + q * 4;
                        atomicAdd(dst + 0, acc[0]);
                        atomicAdd(dst + 1, acc[1]);
                        atomicAdd(dst + 2, acc[2]);
                        atomicAdd(dst + 3, acc[3]);
                        break;
                    }
                    tk -= rT;
                    const int zT = 32 * S;
                    if (tk < zT) {
                        const int q = tk & 31, sgm = tk >> 5;
                        float acc[4] = {0.f, 0.f, 0.f, 0.f};
                        dot_g4db(CZ[i] + (size_t)(sgm * 128) * 128 + q * 4, 128,
                                 h_s + sgm * 128, acc);
                        float* dst = zacc + (i << 7) + q * 4;
                        atomicAdd(dst + 0, acc[0]);
                        atomicAdd(dst + 1, acc[1]);
                        atomicAdd(dst + 2, acc[2]);
                        atomicAdd(dst + 3, acc[3]);
                        break;
                    }
                    tk -= zT;
                }
            }
        }
        __syncthreads();

        // ---- pass 2: rh = sigmoid(racc) * h --------------------------------
        for (int s = tid; s < LR; s += 512) {
            int a = 0; while (a + 1 < na && s >= pb[a + 1]) a++;
            const int i = act[a], j = s - pb[a];
            rh_s[OFF[i] + j] = sigmoidf_(racc[OFF[i] + j]) * h_s[j];
        }
        __syncthreads();

        // ---- pass 3: hn-dots into hacc -------------------------------------
        int total3 = 128;
        for (int a = 1; a < na; a++) total3 += 32 * (act[a] + 1);
        for (int task = tid; task < total3; task += 512) {
            int tk = task;
            if (tk < 128) {
                const int q = tk & 31, sgm = tk >> 5;
                const int col = q * 4, k0 = sgm * 32;
                float4 acc = dot_s4_32(ch0_s + (k0 << 7) + col, rh_s + k0);
                float* dst = hacc + col;
                atomicAdd(dst + 0, acc.x);
                atomicAdd(dst + 1, acc.y);
                atomicAdd(dst + 2, acc.z);
                atomicAdd(dst + 3, acc.w);
            } else {
                tk -= 128;
                for (int a = 1; a < na; a++) {
                    const int i = act[a], S = i + 1;
                    const int hT = 32 * S;
                    if (tk < hT) {
                        const int q = tk & 31, sgm = tk >> 5;
                        float acc[4] = {0.f, 0.f, 0.f, 0.f};
                        dot_g4db(CH[i] + (size_t)(sgm * 128) * 128 + q * 4, 128,
                                 rh_s + OFF[i] + sgm * 128, acc);
                        float* dst = hacc + (i << 7) + q * 4;
                        atomicAdd(dst + 0, acc[0]);
                        atomicAdd(dst + 1, acc[1]);
                        atomicAdd(dst + 2, acc[2]);
                        atomicAdd(dst + 3, acc[3]);
                        break;
                    }
                    tk -= hT;
                }
            }
        }
        __syncthreads();

        // ---- pass 4: gates + h update --------------------------------------
        for (int s = tid; s < (na << 7); s += 512) {
            const int i = act[s >> 7], j = s & 127, col = (i << 7) + j;
            const float z  = sigmoidf_(zacc[col]);
            const float hn = sigmoidf_(hacc[col]);
            h_s[col] = z * hn + (1.0f - z) * h_s[col];
        }
        __syncthreads();

        out[xrow + tid] = h_s[tid];
    }
}

// ---------------------------------------------------------------------------
extern "C" void kernel_launch(void* const* d_in, const int* in_sizes, int n_in,
                              void* d_out, int out_size) {
    (void)in_sizes; (void)n_in; (void)out_size;
    const float* x  = (const float*)d_in[0];
    const float* W  = (const float*)d_in[1];
    const float* bb = (const float*)d_in[2];
    const float* Wr = (const float*)d_in[3];
    const float* br = (const float*)d_in[4];
    const float* Wz = (const float*)d_in[5];
    const float* bz = (const float*)d_in[6];
    const float* ch[4]; const float* cr[4]; const float* cz[4];
    for (int i = 0; i < 4; i++) {
        ch[i] = (const float*)d_in[7 + 3 * i + 0];
        cr[i] = (const float*)d_in[7 + 3 * i + 1];
        cz[i] = (const float*)d_in[7 + 3 * i + 2];
    }
    float* out = (float*)d_out;

    dim3 grid(GN / BN, GM / BM, 3);
    gemm3_kernel<<<grid, 256>>>(x, W, bb, Wr, br, Wz, bz);

    size_t smem_bytes = (4096 + 3 * 16384) * sizeof(float); // 212,992 B
    cudaFuncSetAttribute(scan_kernel,
                         cudaFuncAttributeMaxDynamicSharedMemorySize,
                         (int)smem_bytes);
    scan_kernel<<<NBATCH, 512, smem_bytes>>>(
        ch[0], cr[0], cz[0],
        ch[1], cr[1], cz[1],
        ch[2], cr[2], cz[2],
        ch[3], cr[3], cz[3],
        out);
}

// round 6
// speedup vs baseline: 5.3697x; 1.1256x over previous
#include <cuda_runtime.h>
#include <cstdint>

// ---------------------------------------------------------------------------
// ClockworkGRU:
//   Phase A: proj[z] = x @ Wz + bz for z in {W, Wr, Wz}   (3x SGEMM, fp32)
//   Phase B: sequential scan, one 2-CTA cluster per batch element
//            (column-split, h/rh exchanged via DSMEM).
// ---------------------------------------------------------------------------

#define GM 32768   // B*SEQ rows
#define GK 512
#define GN 512
#define SEQ_LEN 512
#define NBATCH 64

__device__ float g_proj[3ull * GM * GN];

// ---------------- packed f32x2 helpers (GEMM) --------------------------------
__device__ __forceinline__ unsigned long long pack2(float x, float y) {
    unsigned long long r;
    asm("mov.b64 %0, {%1, %2};" : "=l"(r) : "f"(x), "f"(y));
    return r;
}
__device__ __forceinline__ void fma2(unsigned long long& d,
                                     unsigned long long a,
                                     unsigned long long b) {
    asm("fma.rn.f32x2 %0, %1, %2, %0;" : "+l"(d) : "l"(a), "l"(b));
}
__device__ __forceinline__ float2 unpack2(unsigned long long v) {
    float2 r;
    asm("mov.b64 {%0, %1}, %2;" : "=f"(r.x), "=f"(r.y) : "l"(v));
    return r;
}

__device__ __forceinline__ float sigmoidf_(float x) {
    return 1.0f / (1.0f + __expf(-x));
}

// ---------------- cluster / DSMEM helpers ------------------------------------
__device__ __forceinline__ uint32_t smem_u32(const void* p) {
    return (uint32_t)__cvta_generic_to_shared(p);
}
__device__ __forceinline__ uint32_t mapa_u32(uint32_t addr, uint32_t rank) {
    uint32_t r;
    asm("mapa.shared::cluster.u32 %0, %1, %2;" : "=r"(r) : "r"(addr), "r"(rank));
    return r;
}
__device__ __forceinline__ void st_cluster_f32(uint32_t a, float v) {
    asm volatile("st.shared::cluster.f32 [%0], %1;" :: "r"(a), "f"(v) : "memory");
}
#define CLUSTER_SYNC() do {                                           \
    asm volatile("barrier.cluster.arrive.aligned;" ::: "memory");     \
    asm volatile("barrier.cluster.wait.aligned;"   ::: "memory");     \
} while (0)

// ---------------------------------------------------------------------------
// GEMM (unchanged — measured ~0.95 ms)
// ---------------------------------------------------------------------------
#define BM 128
#define BN 128
#define BKK 8

__global__ void __launch_bounds__(256) gemm3_kernel(
    const float* __restrict__ A,
    const float* __restrict__ W0, const float* __restrict__ b0,
    const float* __restrict__ W1, const float* __restrict__ b1,
    const float* __restrict__ W2, const float* __restrict__ b2)
{
    __shared__ float As[BKK][BM];
    __shared__ float Bs[BKK][BN];

    const int z = blockIdx.z;
    const float* W    = (z == 0) ? W0 : (z == 1 ? W1 : W2);
    const float* bias = (z == 0) ? b0 : (z == 1 ? b1 : b2);
    float* C = g_proj + (size_t)z * GM * GN;

    const int m0 = blockIdx.y * BM;
    const int n0 = blockIdx.x * BN;
    const int tid = threadIdx.x;

    const int a_row = tid >> 1;
    const int a_k   = (tid & 1) * 4;
    const int b_row = tid >> 5;
    const int b_col = (tid & 31) * 4;

    const int warp = tid >> 5;
    const int lane = tid & 31;
    const int row0 = (warp & 3) * 32 + (lane & 3) * 8;
    const int col0 = (warp >> 2) * 64 + (lane >> 2) * 8;

    unsigned long long acc[8][4];
#pragma unroll
    for (int i = 0; i < 8; i++)
#pragma unroll
        for (int j = 0; j < 4; j++) acc[i][j] = 0ull;

    const float* Aptr = A + (size_t)(m0 + a_row) * GK + a_k;
    const float* Wptr = W + (size_t)b_row * GN + n0 + b_col;

    float4 ra = *(const float4*)Aptr;
    float4 rb = *(const float4*)Wptr;

    const int KT = GK / BKK;
    for (int kt = 0; kt < KT; kt++) {
        As[a_k + 0][a_row] = ra.x;
        As[a_k + 1][a_row] = ra.y;
        As[a_k + 2][a_row] = ra.z;
        As[a_k + 3][a_row] = ra.w;
        *(float4*)&Bs[b_row][b_col] = rb;
        __syncthreads();

        if (kt + 1 < KT) {
            ra = *(const float4*)(Aptr + (kt + 1) * BKK);
            rb = *(const float4*)(Wptr + (size_t)(kt + 1) * BKK * GN);
        }

#pragma unroll
        for (int k = 0; k < BKK; k++) {
            float4 a0 = *(const float4*)&As[k][row0];
            float4 a1 = *(const float4*)&As[k][row0 + 4];
            ulonglong2 bq0 = *(const ulonglong2*)&Bs[k][col0];
            ulonglong2 bq1 = *(const ulonglong2*)&Bs[k][col0 + 4];
            unsigned long long av[8];
            av[0] = pack2(a0.x, a0.x); av[1] = pack2(a0.y, a0.y);
            av[2] = pack2(a0.z, a0.z); av[3] = pack2(a0.w, a0.w);
            av[4] = pack2(a1.x, a1.x); av[5] = pack2(a1.y, a1.y);
            av[6] = pack2(a1.z, a1.z); av[7] = pack2(a1.w, a1.w);
#pragma unroll
            for (int i = 0; i < 8; i++) {
                fma2(acc[i][0], av[i], bq0.x);
                fma2(acc[i][1], av[i], bq0.y);
                fma2(acc[i][2], av[i], bq1.x);
                fma2(acc[i][3], av[i], bq1.y);
            }
        }
        __syncthreads();
    }

    float bb[8];
#pragma unroll
    for (int j = 0; j < 8; j++) bb[j] = bias[n0 + col0 + j];

#pragma unroll
    for (int i = 0; i < 8; i++) {
        float o[8];
#pragma unroll
        for (int jp = 0; jp < 4; jp++) {
            float2 v = unpack2(acc[i][jp]);
            o[2 * jp]     = v.x + bb[2 * jp];
            o[2 * jp + 1] = v.y + bb[2 * jp + 1];
        }
        size_t base = (size_t)(m0 + row0 + i) * GN + n0 + col0;
        *(float4*)&C[base]     = make_float4(o[0], o[1], o[2], o[3]);
        *(float4*)&C[base + 4] = make_float4(o[4], o[5], o[6], o[7]);
    }
}

// ---------------------------------------------------------------------------
// Scan v5 — 2-CTA cluster per batch, column-split. Per-CTA streamed bytes
// halved; 128 CTAs fill 128 of 148 SMs (one wave).
// ---------------------------------------------------------------------------

// streaming 4-col dot over a KSEG-deep k segment, double-buffered 8+8
template<int KSEG>
__device__ __forceinline__ void dot_g4db(const float* __restrict__ w, int stride,
                                         const float* __restrict__ hv,
                                         float acc[4])
{
    float4 A[8], B[8];
#pragma unroll
    for (int r = 0; r < 8; r++) A[r] = *(const float4*)(w + (size_t)r * stride);
    for (int kb = 0; kb < KSEG; kb += 16) {
#pragma unroll
        for (int r = 0; r < 8; r++)
            B[r] = *(const float4*)(w + (size_t)(kb + 8 + r) * stride);
#pragma unroll
        for (int r = 0; r < 8; r++) {
            float hk = hv[kb + r];
            acc[0] = fmaf(hk, A[r].x, acc[0]);
            acc[1] = fmaf(hk, A[r].y, acc[1]);
            acc[2] = fmaf(hk, A[r].z, acc[2]);
            acc[3] = fmaf(hk, A[r].w, acc[3]);
        }
        if (kb + 16 < KSEG) {
#pragma unroll
            for (int r = 0; r < 8; r++)
                A[r] = *(const float4*)(w + (size_t)(kb + 16 + r) * stride);
        }
#pragma unroll
        for (int r = 0; r < 8; r++) {
            float hk = hv[kb + 8 + r];
            acc[0] = fmaf(hk, B[r].x, acc[0]);
            acc[1] = fmaf(hk, B[r].y, acc[1]);
            acc[2] = fmaf(hk, B[r].z, acc[2]);
            acc[3] = fmaf(hk, B[r].w, acc[3]);
        }
    }
}

// SMEM 4-col dot over a KSEG-deep k segment (block 0 half, row stride 64)
template<int KSEG>
__device__ __forceinline__ float4 dot_s4(const float* __restrict__ w,
                                         const float* __restrict__ hv)
{
    float a0 = 0.f, a1 = 0.f, a2 = 0.f, a3 = 0.f;
#pragma unroll
    for (int k = 0; k < KSEG; k++) {
        float hk = hv[k];
        float4 ww = *(const float4*)&w[k << 6];
        a0 = fmaf(hk, ww.x, a0);
        a1 = fmaf(hk, ww.y, a1);
        a2 = fmaf(hk, ww.z, a2);
        a3 = fmaf(hk, ww.w, a3);
    }
    return make_float4(a0, a1, a2, a3);
}

__global__ void __launch_bounds__(512, 1) __cluster_dims__(2, 1, 1)
scan_kernel(
    const float* __restrict__ ch0, const float* __restrict__ cr0, const float* __restrict__ cz0,
    const float* __restrict__ ch1, const float* __restrict__ cr1, const float* __restrict__ cz1,
    const float* __restrict__ ch2, const float* __restrict__ cr2, const float* __restrict__ cz2,
    const float* __restrict__ ch3, const float* __restrict__ cr3, const float* __restrict__ cz3,
    float* __restrict__ out)
{
    extern __shared__ float smem[];
    float* h_s   = smem;              // 512  (full h, replicated)
    float* rh_s  = smem + 512;        // 1280 (full rh, replicated)
    float* racc  = smem + 1792;       // 1280 (own cols only used)
    float* zacc  = smem + 3072;       // 512
    float* hacc  = smem + 3584;       // 512
    float* cr0_s = smem + 4096;       // 8192 (block0 half: 128 x 64)
    float* cz0_s = cr0_s + 8192;      // 8192
    float* ch0_s = cz0_s + 8192;      // 8192

    const int b    = blockIdx.x >> 1;
    const int rank = blockIdx.x & 1;
    const int peer = rank ^ 1;
    const int tid  = threadIdx.x;

    // preload OWN HALF of block-0 matrices (3 x 128x64 = 96 KB)
    for (int i = tid; i < 2048; i += 512) {
        const int row = i >> 4, c4 = (i & 15) * 4;
        const int gsrc = row * 128 + rank * 64 + c4;
        const int ldst = row * 64 + c4;
        *(float4*)&cr0_s[ldst] = *(const float4*)&cr0[gsrc];
        *(float4*)&cz0_s[ldst] = *(const float4*)&cz0[gsrc];
        *(float4*)&ch0_s[ldst] = *(const float4*)&ch0[gsrc];
    }
    h_s[tid] = 0.0f;
    __syncthreads();
    CLUSTER_SYNC();

    const uint32_t peer_rh = mapa_u32(smem_u32(rh_s), (uint32_t)peer);
    const uint32_t peer_h  = mapa_u32(smem_u32(h_s),  (uint32_t)peer);

    const float* xt  = g_proj;
    const float* xrt = g_proj + (size_t)GM * GN;
    const float* xzt = g_proj + 2ull * GM * GN;

    const float* CR[4] = {cr0, cr1, cr2, cr3};
    const float* CZ[4] = {cz0, cz1, cz2, cz3};
    const float* CH[4] = {ch0, ch1, ch2, ch3};
    const int OFF[4] = {0, 128, 384, 768};

    for (int t = 0; t < SEQ_LEN; t++) {
        int act[4]; int na = 0;
        act[na++] = 0;
        if ((t & 1) == 0) act[na++] = 1;
        if ((t & 3) == 0) act[na++] = 2;
        if ((t & 7) == 0) act[na++] = 3;

        // own r-column bookkeeping: block i contributes (i+1)*64 own cols
        int pbr[5]; pbr[0] = 0;
        for (int a = 0; a < na; a++) pbr[a + 1] = pbr[a] + ((act[a] + 1) << 6);
        const int LRo = pbr[na];
        const int ZH  = na << 6;   // own z/h cols

        const size_t xrow = ((size_t)b * SEQ_LEN + t) * GN;

        // ---- init accumulators with biases (own cols) ----------------------
        for (int s = tid; s < LRo; s += 512) {
            int a = 0; while (a + 1 < na && s >= pbr[a + 1]) a++;
            const int i = act[a];
            const int j = rank * ((i + 1) << 6) + (s - pbr[a]);
            racc[OFF[i] + j] = xrt[xrow + j];
        }
        for (int s = tid; s < ZH; s += 512) {
            const int i = act[s >> 6];
            const int col = (i << 7) + (rank << 6) + (s & 63);
            zacc[col] = xzt[xrow + col];
            hacc[col] = xt[xrow + col];
        }
        __syncthreads();

        // ---- pass 1: r-dots + z-dots (own cols, k-split) --------------------
        int total1 = 128;   // block0: 64 r + 64 z (16 quads x 4 segs of 32)
        for (int a = 1; a < na; a++) {
            const int i = act[a], S = i + 1;
            total1 += ((i + 1) * 16 + 16) * S;
        }
        for (int task = tid; task < total1; task += 512) {
            int tk = task;
            if (tk < 128) {
                const bool isZ = tk >= 64;
                const int idx = tk & 63;
                const int q = idx & 15, sgm = idx >> 4;
                const int cl = q * 4;                 // local col in half
                const float* w = (isZ ? cz0_s : cr0_s) + (sgm * 32) * 64 + cl;
                float4 acc = dot_s4<32>(w, h_s + sgm * 32);
                float* dst = (isZ ? zacc : racc) + (rank << 6) + cl;
                atomicAdd(dst + 0, acc.x);
                atomicAdd(dst + 1, acc.y);
                atomicAdd(dst + 2, acc.z);
                atomicAdd(dst + 3, acc.w);
            } else {
                tk -= 128;
                for (int a = 1; a < na; a++) {
                    const int i = act[a], S = i + 1;
                    const int m = (i + 1) << 7, hm = (i + 1) << 6;
                    const int rQ = (i + 1) * 16;
                    const int rT = rQ * S;
                    if (tk < rT) {
                        const int q = tk % rQ, sgm = tk / rQ;
                        float acc[4] = {0.f, 0.f, 0.f, 0.f};
                        dot_g4db<128>(CR[i] + (size_t)(sgm * 128) * m
                                            + rank * hm + q * 4,
                                      m, h_s + sgm * 128, acc);
                        float* dst = racc + OFF[i] + rank * hm + q * 4;
                        atomicAdd(dst + 0, acc[0]);
                        atomicAdd(dst + 1, acc[1]);
                        atomicAdd(dst + 2, acc[2]);
                        atomicAdd(dst + 3, acc[3]);
                        break;
                    }
                    tk -= rT;
                    const int zT = 16 * S;
                    if (tk < zT) {
                        const int q = tk & 15, sgm = tk >> 4;
                        float acc[4] = {0.f, 0.f, 0.f, 0.f};
                        dot_g4db<128>(CZ[i] + (size_t)(sgm * 128) * 128
                                            + (rank << 6) + q * 4,
                                      128, h_s + sgm * 128, acc);
                        float* dst = zacc + (i << 7) + (rank << 6) + q * 4;
                        atomicAdd(dst + 0, acc[0]);
                        atomicAdd(dst + 1, acc[1]);
                        atomicAdd(dst + 2, acc[2]);
                        atomicAdd(dst + 3, acc[3]);
                        break;
                    }
                    tk -= zT;
                }
            }
        }
        __syncthreads();

        // ---- pass 2: rh (own r cols) local + peer ---------------------------
        for (int s = tid; s < LRo; s += 512) {
            int a = 0; while (a + 1 < na && s >= pbr[a + 1]) a++;
            const int i = act[a];
            const int j = rank * ((i + 1) << 6) + (s - pbr[a]);
            const float v = sigmoidf_(racc[OFF[i] + j]) * h_s[j];
            rh_s[OFF[i] + j] = v;
            st_cluster_f32(peer_rh + (uint32_t)(OFF[i] + j) * 4u, v);
        }
        CLUSTER_SYNC();   // full rh visible in both ranks

        // ---- pass 3: hn-dots (own cols, k-split) ----------------------------
        int total3 = 128;   // block0: 16 quads x 8 segs of 16
        for (int a = 1; a < na; a++) total3 += 32 * (act[a] + 1);
        for (int task = tid; task < total3; task += 512) {
            int tk = task;
            if (tk < 128) {
                const int q = tk & 15, sgm = tk >> 4;
                const int cl = q * 4;
                float4 acc = dot_s4<16>(ch0_s + (sgm * 16) * 64 + cl,
                                        rh_s + sgm * 16);
                float* dst = hacc + (rank << 6) + cl;
                atomicAdd(dst + 0, acc.x);
                atomicAdd(dst + 1, acc.y);
                atomicAdd(dst + 2, acc.z);
                atomicAdd(dst + 3, acc.w);
            } else {
                tk -= 128;
                for (int a = 1; a < na; a++) {
                    const int i = act[a];
                    const int hT = 32 * (i + 1);   // 16 quads x 2(i+1) segs of 64
                    if (tk < hT) {
                        const int q = tk & 15, sgm = tk >> 4;
                        float acc[4] = {0.f, 0.f, 0.f, 0.f};
                        dot_g4db<64>(CH[i] + (size_t)(sgm * 64) * 128
                                           + (rank << 6) + q * 4,
                                     128, rh_s + OFF[i] + sgm * 64, acc);
                        float* dst = hacc + (i << 7) + (rank << 6) + q * 4;
                        atomicAdd(dst + 0, acc[0]);
                        atomicAdd(dst + 1, acc[1]);
                        atomicAdd(dst + 2, acc[2]);
                        atomicAdd(dst + 3, acc[3]);
                        break;
                    }
                    tk -= hT;
                }
            }
        }
        __syncthreads();

        // ---- pass 4: gates + h update (own cols) local + peer ---------------
        for (int s = tid; s < ZH; s += 512) {
            const int i = act[s >> 6];
            const int col = (i << 7) + (rank << 6) + (s & 63);
            const float z  = sigmoidf_(zacc[col]);
            const float hn = sigmoidf_(hacc[col]);
            const float v  = z * hn + (1.0f - z) * h_s[col];
            h_s[col] = v;
            st_cluster_f32(peer_h + (uint32_t)col * 4u, v);
        }
        CLUSTER_SYNC();   // full h visible in both ranks

        if (tid < 256)
            out[xrow + (rank << 8) + tid] = h_s[(rank << 8) + tid];
    }
}

// ---------------------------------------------------------------------------
extern "C" void kernel_launch(void* const* d_in, const int* in_sizes, int n_in,
                              void* d_out, int out_size) {
    (void)in_sizes; (void)n_in; (void)out_size;
    const float* x  = (const float*)d_in[0];
    const float* W  = (const float*)d_in[1];
    const float* bb = (const float*)d_in[2];
    const float* Wr = (const float*)d_in[3];
    const float* br = (const float*)d_in[4];
    const float* Wz = (const float*)d_in[5];
    const float* bz = (const float*)d_in[6];
    const float* ch[4]; const float* cr[4]; const float* cz[4];
    for (int i = 0; i < 4; i++) {
        ch[i] = (const float*)d_in[7 + 3 * i + 0];
        cr[i] = (const float*)d_in[7 + 3 * i + 1];
        cz[i] = (const float*)d_in[7 + 3 * i + 2];
    }
    float* out = (float*)d_out;

    dim3 grid(GN / BN, GM / BM, 3);
    gemm3_kernel<<<grid, 256>>>(x, W, bb, Wr, br, Wz, bz);

    size_t smem_bytes = (4096 + 3 * 8192) * sizeof(float);  // 114,688 B
    cudaFuncSetAttribute(scan_kernel,
                         cudaFuncAttributeMaxDynamicSharedMemorySize,
                         (int)smem_bytes);
    scan_kernel<<<NBATCH * 2, 512, smem_bytes>>>(
        ch[0], cr[0], cz[0],
        ch[1], cr[1], cz[1],
        ch[2], cr[2], cz[2],
        ch[3], cr[3], cz[3],
        out);
}

// round 7
// speedup vs baseline: 6.2613x; 1.1660x over previous
#include <cuda_runtime.h>
#include <cstdint>

// ---------------------------------------------------------------------------
// ClockworkGRU:
//   Phase A: proj[z] = x @ Wz + bz for z in {W, Wr, Wz}   (3x SGEMM, fp32)
//   Phase B: scan — 4-CTA cluster per PAIR of batch elements.
//            Each CTA owns 1/4 of the columns and 2 batch rows ->
//            every loaded weight feeds 8 FMAs. Blocks 0 & 1 SMEM-cached.
// ---------------------------------------------------------------------------

#define GM 32768
#define GK 512
#define GN 512
#define SEQ_LEN 512
#define NBATCH 64

__device__ float g_proj[3ull * GM * GN];

// ---------------- packed f32x2 helpers (GEMM) --------------------------------
__device__ __forceinline__ unsigned long long pack2(float x, float y) {
    unsigned long long r;
    asm("mov.b64 %0, {%1, %2};" : "=l"(r) : "f"(x), "f"(y));
    return r;
}
__device__ __forceinline__ void fma2(unsigned long long& d,
                                     unsigned long long a,
                                     unsigned long long b) {
    asm("fma.rn.f32x2 %0, %1, %2, %0;" : "+l"(d) : "l"(a), "l"(b));
}
__device__ __forceinline__ float2 unpack2(unsigned long long v) {
    float2 r;
    asm("mov.b64 {%0, %1}, %2;" : "=f"(r.x), "=f"(r.y) : "l"(v));
    return r;
}
__device__ __forceinline__ float sigmoidf_(float x) {
    return 1.0f / (1.0f + __expf(-x));
}

// ---------------- cluster / DSMEM helpers ------------------------------------
__device__ __forceinline__ uint32_t smem_u32(const void* p) {
    return (uint32_t)__cvta_generic_to_shared(p);
}
__device__ __forceinline__ uint32_t mapa_u32(uint32_t addr, uint32_t rank) {
    uint32_t r;
    asm("mapa.shared::cluster.u32 %0, %1, %2;" : "=r"(r) : "r"(addr), "r"(rank));
    return r;
}
__device__ __forceinline__ void st_cluster_b64(uint32_t a, float x, float y) {
    unsigned long long v = pack2(x, y);
    asm volatile("st.shared::cluster.b64 [%0], %1;" :: "r"(a), "l"(v) : "memory");
}
#define CLUSTER_SYNC() do {                                           \
    asm volatile("barrier.cluster.arrive.aligned;" ::: "memory");     \
    asm volatile("barrier.cluster.wait.aligned;"   ::: "memory");     \
} while (0)

// ---------------------------------------------------------------------------
// GEMM (unchanged — ~0.95 ms)
// ---------------------------------------------------------------------------
#define BM 128
#define BN 128
#define BKK 8

__global__ void __launch_bounds__(256) gemm3_kernel(
    const float* __restrict__ A,
    const float* __restrict__ W0, const float* __restrict__ b0,
    const float* __restrict__ W1, const float* __restrict__ b1,
    const float* __restrict__ W2, const float* __restrict__ b2)
{
    __shared__ float As[BKK][BM];
    __shared__ float Bs[BKK][BN];

    const int z = blockIdx.z;
    const float* W    = (z == 0) ? W0 : (z == 1 ? W1 : W2);
    const float* bias = (z == 0) ? b0 : (z == 1 ? b1 : b2);
    float* C = g_proj + (size_t)z * GM * GN;

    const int m0 = blockIdx.y * BM;
    const int n0 = blockIdx.x * BN;
    const int tid = threadIdx.x;

    const int a_row = tid >> 1;
    const int a_k   = (tid & 1) * 4;
    const int b_row = tid >> 5;
    const int b_col = (tid & 31) * 4;

    const int warp = tid >> 5;
    const int lane = tid & 31;
    const int row0 = (warp & 3) * 32 + (lane & 3) * 8;
    const int col0 = (warp >> 2) * 64 + (lane >> 2) * 8;

    unsigned long long acc[8][4];
#pragma unroll
    for (int i = 0; i < 8; i++)
#pragma unroll
        for (int j = 0; j < 4; j++) acc[i][j] = 0ull;

    const float* Aptr = A + (size_t)(m0 + a_row) * GK + a_k;
    const float* Wptr = W + (size_t)b_row * GN + n0 + b_col;

    float4 ra = *(const float4*)Aptr;
    float4 rb = *(const float4*)Wptr;

    const int KT = GK / BKK;
    for (int kt = 0; kt < KT; kt++) {
        As[a_k + 0][a_row] = ra.x;
        As[a_k + 1][a_row] = ra.y;
        As[a_k + 2][a_row] = ra.z;
        As[a_k + 3][a_row] = ra.w;
        *(float4*)&Bs[b_row][b_col] = rb;
        __syncthreads();

        if (kt + 1 < KT) {
            ra = *(const float4*)(Aptr + (kt + 1) * BKK);
            rb = *(const float4*)(Wptr + (size_t)(kt + 1) * BKK * GN);
        }

#pragma unroll
        for (int k = 0; k < BKK; k++) {
            float4 a0 = *(const float4*)&As[k][row0];
            float4 a1 = *(const float4*)&As[k][row0 + 4];
            ulonglong2 bq0 = *(const ulonglong2*)&Bs[k][col0];
            ulonglong2 bq1 = *(const ulonglong2*)&Bs[k][col0 + 4];
            unsigned long long av[8];
            av[0] = pack2(a0.x, a0.x); av[1] = pack2(a0.y, a0.y);
            av[2] = pack2(a0.z, a0.z); av[3] = pack2(a0.w, a0.w);
            av[4] = pack2(a1.x, a1.x); av[5] = pack2(a1.y, a1.y);
            av[6] = pack2(a1.z, a1.z); av[7] = pack2(a1.w, a1.w);
#pragma unroll
            for (int i = 0; i < 8; i++) {
                fma2(acc[i][0], av[i], bq0.x);
                fma2(acc[i][1], av[i], bq0.y);
                fma2(acc[i][2], av[i], bq1.x);
                fma2(acc[i][3], av[i], bq1.y);
            }
        }
        __syncthreads();
    }

    float bb[8];
#pragma unroll
    for (int j = 0; j < 8; j++) bb[j] = bias[n0 + col0 + j];

#pragma unroll
    for (int i = 0; i < 8; i++) {
        float o[8];
#pragma unroll
        for (int jp = 0; jp < 4; jp++) {
            float2 v = unpack2(acc[i][jp]);
            o[2 * jp]     = v.x + bb[2 * jp];
            o[2 * jp + 1] = v.y + bb[2 * jp + 1];
        }
        size_t base = (size_t)(m0 + row0 + i) * GN + n0 + col0;
        *(float4*)&C[base]     = make_float4(o[0], o[1], o[2], o[3]);
        *(float4*)&C[base + 4] = make_float4(o[4], o[5], o[6], o[7]);
    }
}

// ---------------------------------------------------------------------------
// Scan v6 dots: 4 cols x 2 rows (pass1) / 4 cols x 1 row (pass3)
// ---------------------------------------------------------------------------

// global, 64-deep, double-buffered 8+8, 2 rows
__device__ __forceinline__ void dot_g42_64(const float* __restrict__ w, int stride,
                                           const float* __restrict__ h0,
                                           const float* __restrict__ h1,
                                           float* a0, float* a1)
{
    float4 A[8], B[8];
#pragma unroll
    for (int r = 0; r < 8; r++) A[r] = *(const float4*)(w + (size_t)r * stride);
#pragma unroll
    for (int kb = 0; kb < 64; kb += 16) {
#pragma unroll
        for (int r = 0; r < 8; r++)
            B[r] = *(const float4*)(w + (size_t)(kb + 8 + r) * stride);
#pragma unroll
        for (int r = 0; r < 8; r++) {
            float x0 = h0[kb + r], x1 = h1[kb + r];
            a0[0] = fmaf(x0, A[r].x, a0[0]); a0[1] = fmaf(x0, A[r].y, a0[1]);
            a0[2] = fmaf(x0, A[r].z, a0[2]); a0[3] = fmaf(x0, A[r].w, a0[3]);
            a1[0] = fmaf(x1, A[r].x, a1[0]); a1[1] = fmaf(x1, A[r].y, a1[1]);
            a1[2] = fmaf(x1, A[r].z, a1[2]); a1[3] = fmaf(x1, A[r].w, a1[3]);
        }
        if (kb + 16 < 64) {
#pragma unroll
            for (int r = 0; r < 8; r++)
                A[r] = *(const float4*)(w + (size_t)(kb + 16 + r) * stride);
        }
#pragma unroll
        for (int r = 0; r < 8; r++) {
            float x0 = h0[kb + 8 + r], x1 = h1[kb + 8 + r];
            a0[0] = fmaf(x0, B[r].x, a0[0]); a0[1] = fmaf(x0, B[r].y, a0[1]);
            a0[2] = fmaf(x0, B[r].z, a0[2]); a0[3] = fmaf(x0, B[r].w, a0[3]);
            a1[0] = fmaf(x1, B[r].x, a1[0]); a1[1] = fmaf(x1, B[r].y, a1[1]);
            a1[2] = fmaf(x1, B[r].z, a1[2]); a1[3] = fmaf(x1, B[r].w, a1[3]);
        }
    }
}

// global, 64-deep, double-buffered, 1 row
__device__ __forceinline__ void dot_g41_64(const float* __restrict__ w, int stride,
                                           const float* __restrict__ hv, float* a)
{
    float4 A[8], B[8];
#pragma unroll
    for (int r = 0; r < 8; r++) A[r] = *(const float4*)(w + (size_t)r * stride);
#pragma unroll
    for (int kb = 0; kb < 64; kb += 16) {
#pragma unroll
        for (int r = 0; r < 8; r++)
            B[r] = *(const float4*)(w + (size_t)(kb + 8 + r) * stride);
#pragma unroll
        for (int r = 0; r < 8; r++) {
            float x = hv[kb + r];
            a[0] = fmaf(x, A[r].x, a[0]); a[1] = fmaf(x, A[r].y, a[1]);
            a[2] = fmaf(x, A[r].z, a[2]); a[3] = fmaf(x, A[r].w, a[3]);
        }
        if (kb + 16 < 64) {
#pragma unroll
            for (int r = 0; r < 8; r++)
                A[r] = *(const float4*)(w + (size_t)(kb + 16 + r) * stride);
        }
#pragma unroll
        for (int r = 0; r < 8; r++) {
            float x = hv[kb + 8 + r];
            a[0] = fmaf(x, B[r].x, a[0]); a[1] = fmaf(x, B[r].y, a[1]);
            a[2] = fmaf(x, B[r].z, a[2]); a[3] = fmaf(x, B[r].w, a[3]);
        }
    }
}

// smem dot, KSEG deep, stride STR, 2 rows
template<int KSEG, int STR>
__device__ __forceinline__ void dot_s42(const float* __restrict__ w,
                                        const float* __restrict__ h0,
                                        const float* __restrict__ h1,
                                        float* a0, float* a1)
{
#pragma unroll
    for (int k = 0; k < KSEG; k++) {
        float4 ww = *(const float4*)&w[k * STR];
        float x0 = h0[k], x1 = h1[k];
        a0[0] = fmaf(x0, ww.x, a0[0]); a0[1] = fmaf(x0, ww.y, a0[1]);
        a0[2] = fmaf(x0, ww.z, a0[2]); a0[3] = fmaf(x0, ww.w, a0[3]);
        a1[0] = fmaf(x1, ww.x, a1[0]); a1[1] = fmaf(x1, ww.y, a1[1]);
        a1[2] = fmaf(x1, ww.z, a1[2]); a1[3] = fmaf(x1, ww.w, a1[3]);
    }
}

// smem dot, KSEG deep, stride STR, 1 row
template<int KSEG, int STR>
__device__ __forceinline__ void dot_s41(const float* __restrict__ w,
                                        const float* __restrict__ hv, float* a)
{
#pragma unroll
    for (int k = 0; k < KSEG; k++) {
        float4 ww = *(const float4*)&w[k * STR];
        float x = hv[k];
        a[0] = fmaf(x, ww.x, a[0]); a[1] = fmaf(x, ww.y, a[1]);
        a[2] = fmaf(x, ww.z, a[2]); a[3] = fmaf(x, ww.w, a[3]);
    }
}

__device__ __forceinline__ void atomic4(float* dst, const float* a,
                                        const float4& b) {
    atomicAdd(dst + 0, a[0] + b.x);
    atomicAdd(dst + 1, a[1] + b.y);
    atomicAdd(dst + 2, a[2] + b.z);
    atomicAdd(dst + 3, a[3] + b.w);
}

// ---------------------------------------------------------------------------
__global__ void __launch_bounds__(512, 1) __cluster_dims__(4, 1, 1)
scan_kernel(
    const float* __restrict__ ch0, const float* __restrict__ cr0, const float* __restrict__ cz0,
    const float* __restrict__ ch1, const float* __restrict__ cr1, const float* __restrict__ cz1,
    const float* __restrict__ ch2, const float* __restrict__ cr2, const float* __restrict__ cz2,
    const float* __restrict__ ch3, const float* __restrict__ cr3, const float* __restrict__ cz3,
    float* __restrict__ out)
{
    extern __shared__ float smem[];
    float* h_s   = smem;              // 2 x 512
    float* rh_s  = smem + 1024;       // 2 x 1280
    float* racc  = smem + 3584;       // 2 x 1280
    float* zacc  = smem + 6144;       // 2 x 512
    float* hacc  = smem + 7168;       // 2 x 512
    float* cr0_s = smem + 8192;       // 128 x 32
    float* cz0_s = smem + 12288;      // 128 x 32
    float* ch0_s = smem + 16384;      // 128 x 32
    float* cr1_s = smem + 20480;      // 256 x 64
    float* cz1_s = smem + 36864;      // 256 x 32
    float* ch1_s = smem + 45056;      // 256 x 32

    const int rank = blockIdx.x & 3;
    const int bp   = blockIdx.x >> 2;       // batch pair index
    const int tid  = threadIdx.x;

    // ---- preload own-column slices of block-0 and block-1 matrices --------
    for (int i = tid; i < 1024; i += 512) {            // 128x32 slices
        const int row = i >> 3, c4 = (i & 7) * 4;
        const int src = row * 128 + rank * 32 + c4;
        const int dst = row * 32 + c4;
        *(float4*)&cr0_s[dst] = *(const float4*)&cr0[src];
        *(float4*)&cz0_s[dst] = *(const float4*)&cz0[src];
        *(float4*)&ch0_s[dst] = *(const float4*)&ch0[src];
    }
    for (int i = tid; i < 4096; i += 512) {            // cr1 256x64
        const int row = i >> 4, c4 = (i & 15) * 4;
        *(float4*)&cr1_s[row * 64 + c4] =
            *(const float4*)&cr1[row * 256 + rank * 64 + c4];
    }
    for (int i = tid; i < 2048; i += 512) {            // cz1/ch1 256x32
        const int row = i >> 3, c4 = (i & 7) * 4;
        *(float4*)&cz1_s[row * 32 + c4] =
            *(const float4*)&cz1[row * 128 + rank * 32 + c4];
        *(float4*)&ch1_s[row * 32 + c4] =
            *(const float4*)&ch1[row * 128 + rank * 32 + c4];
    }
    h_s[tid] = 0.0f; h_s[512 + tid] = 0.0f;
    __syncthreads();
    CLUSTER_SYNC();

    // peer DSMEM addresses
    uint32_t peer_rh[3], peer_h[3];
    {
        int p = 0;
        for (int r = 0; r < 4; r++) {
            if (r == rank) continue;
            peer_rh[p] = mapa_u32(smem_u32(rh_s), (uint32_t)r);
            peer_h[p]  = mapa_u32(smem_u32(h_s),  (uint32_t)r);
            p++;
        }
    }

    const float* xt  = g_proj;
    const float* xrt = g_proj + (size_t)GM * GN;
    const float* xzt = g_proj + 2ull * GM * GN;

    const int OFF[4] = {0, 128, 384, 768};

    for (int t = 0; t < SEQ_LEN; t++) {
        const bool a1 = (t & 1) == 0, a2 = (t & 3) == 0, a3 = (t & 7) == 0;
        int act[4]; int na = 0;
        act[na++] = 0;
        if (a1) act[na++] = 1;
        if (a2) act[na++] = 2;
        if (a3) act[na++] = 3;

        const size_t xr0 = ((size_t)(bp * 2 + 0) * SEQ_LEN + t) * GN;
        const size_t xr1 = ((size_t)(bp * 2 + 1) * SEQ_LEN + t) * GN;

        // ---- zero accumulators --------------------------------------------
        for (int s = tid; s < 2560; s += 512) racc[s] = 0.0f;
        for (int s = tid; s < 1024; s += 512) { zacc[s] = 0.0f; hacc[s] = 0.0f; }
        __syncthreads();

        // ---- pass 1: r-dots + z-dots (own cols, 2 rows per task) ----------
        // boundaries
        const int n_b0r = 64, n_b0z = 64;                       // 8q x 8seg16
        const int n_b1r = a1 ? 64 : 0, n_b1z = a1 ? 32 : 0;     // 16q x 4 / 8q x 4
        const int n_b2r = a2 ? 144 : 0, n_b2z = a2 ? 48 : 0;    // 24q x 6 / 8q x 6
        const int n_b3r = a3 ? 256 : 0, n_b3z = a3 ? 64 : 0;    // 32q x 8 / 8q x 8
        const int total1 = n_b0r + n_b0z + n_b1r + n_b1z +
                           n_b2r + n_b2z + n_b3r + n_b3z;

        for (int task = tid; task < total1; task += 512) {
            int tk = task;
            float A0[4] = {0,0,0,0}, A1[4] = {0,0,0,0};
            float4 B0 = {0,0,0,0}, B1 = {0,0,0,0};
            float *d0, *d1;

            if (tk < n_b0r) {                       // block0 r (SMEM, 16-deep)
                const int q = tk & 7, seg = tk >> 3;
                const int c = q * 4, j = rank * 32 + c;
                if (seg == 0) { B0 = *(const float4*)&xrt[xr0 + j];
                                B1 = *(const float4*)&xrt[xr1 + j]; }
                dot_s42<16, 32>(cr0_s + seg * 16 * 32 + c,
                                h_s + seg * 16, h_s + 512 + seg * 16, A0, A1);
                d0 = racc + j; d1 = racc + 1280 + j;
            } else if ((tk -= n_b0r) < n_b0z) {     // block0 z (SMEM)
                const int q = tk & 7, seg = tk >> 3;
                const int c = q * 4, gc = rank * 32 + c;
                if (seg == 0) { B0 = *(const float4*)&xzt[xr0 + gc];
                                B1 = *(const float4*)&xzt[xr1 + gc]; }
                dot_s42<16, 32>(cz0_s + seg * 16 * 32 + c,
                                h_s + seg * 16, h_s + 512 + seg * 16, A0, A1);
                d0 = zacc + gc; d1 = zacc + 512 + gc;
            } else if ((tk -= n_b0z) < n_b1r) {     // block1 r (SMEM, 64-deep)
                const int q = tk & 15, seg = tk >> 4;
                const int c = q * 4, j = rank * 64 + c;
                if (seg == 0) { B0 = *(const float4*)&xrt[xr0 + j];
                                B1 = *(const float4*)&xrt[xr1 + j]; }
                dot_s42<64, 64>(cr1_s + seg * 64 * 64 + c,
                                h_s + seg * 64, h_s + 512 + seg * 64, A0, A1);
                d0 = racc + 128 + j; d1 = racc + 1280 + 128 + j;
            } else if ((tk -= n_b1r) < n_b1z) {     // block1 z (SMEM)
                const int q = tk & 7, seg = tk >> 3;
                const int c = q * 4, gc = 128 + rank * 32 + c;
                if (seg == 0) { B0 = *(const float4*)&xzt[xr0 + gc];
                                B1 = *(const float4*)&xzt[xr1 + gc]; }
                dot_s42<64, 32>(cz1_s + seg * 64 * 32 + c,
                                h_s + seg * 64, h_s + 512 + seg * 64, A0, A1);
                d0 = zacc + gc; d1 = zacc + 512 + gc;
            } else if ((tk -= n_b1z) < n_b2r) {     // block2 r (global)
                const int q = tk % 24, seg = tk / 24;
                const int j = rank * 96 + q * 4;
                if (seg == 0) { B0 = *(const float4*)&xrt[xr0 + j];
                                B1 = *(const float4*)&xrt[xr1 + j]; }
                dot_g42_64(cr2 + (size_t)(seg * 64) * 384 + j, 384,
                           h_s + seg * 64, h_s + 512 + seg * 64, A0, A1);
                d0 = racc + 384 + j; d1 = racc + 1280 + 384 + j;
            } else if ((tk -= n_b2r) < n_b2z) {     // block2 z (global)
                const int q = tk & 7, seg = tk >> 3;
                const int lc = rank * 32 + q * 4, gc = 256 + lc;
                if (seg == 0) { B0 = *(const float4*)&xzt[xr0 + gc];
                                B1 = *(const float4*)&xzt[xr1 + gc]; }
                dot_g42_64(cz2 + (size_t)(seg * 64) * 128 + lc, 128,
                           h_s + seg * 64, h_s + 512 + seg * 64, A0, A1);
                d0 = zacc + gc; d1 = zacc + 512 + gc;
            } else if ((tk -= n_b2z) < n_b3r) {     // block3 r (global)
                const int q = tk & 31, seg = tk >> 5;
                const int j = rank * 128 + q * 4;
                if (seg == 0) { B0 = *(const float4*)&xrt[xr0 + j];
                                B1 = *(const float4*)&xrt[xr1 + j]; }
                dot_g42_64(cr3 + (size_t)(seg * 64) * 512 + j, 512,
                           h_s + seg * 64, h_s + 512 + seg * 64, A0, A1);
                d0 = racc + 768 + j; d1 = racc + 1280 + 768 + j;
            } else {                                 // block3 z (global)
                tk -= n_b3r;
                const int q = tk & 7, seg = tk >> 3;
                const int lc = rank * 32 + q * 4, gc = 384 + lc;
                if (seg == 0) { B0 = *(const float4*)&xzt[xr0 + gc];
                                B1 = *(const float4*)&xzt[xr1 + gc]; }
                dot_g42_64(cz3 + (size_t)(seg * 64) * 128 + lc, 128,
                           h_s + seg * 64, h_s + 512 + seg * 64, A0, A1);
                d0 = zacc + gc; d1 = zacc + 512 + gc;
            }
            atomic4(d0, A0, B0);
            atomic4(d1, A1, B1);
        }
        __syncthreads();

        // ---- pass 2: rh (own r cols) local + 3 peers ------------------------
        {
            int npairs = 0;
            int pcount[4];
            for (int a = 0; a < na; a++) {
                pcount[a] = (act[a] + 1) * 16;   // (m/4)/2 pairs
                npairs += pcount[a];
            }
            for (int s = tid; s < 2 * npairs; s += 512) {
                const int row = s & 1;
                int p = s >> 1;
                int i = 0;
                for (int a = 0; a < na; a++) {
                    if (p < pcount[a]) { i = act[a]; break; }
                    p -= pcount[a];
                }
                const int j = rank * ((i + 1) * 32) + p * 2;
                const int idx = OFF[i] + j;
                const float* rc = racc + row * 1280;
                const float* hh = h_s + row * 512;
                const float v0 = sigmoidf_(rc[idx])     * hh[j];
                const float v1 = sigmoidf_(rc[idx + 1]) * hh[j + 1];
                rh_s[row * 1280 + idx]     = v0;
                rh_s[row * 1280 + idx + 1] = v1;
                const uint32_t off = (uint32_t)(row * 1280 + idx) * 4u;
                st_cluster_b64(peer_rh[0] + off, v0, v1);
                st_cluster_b64(peer_rh[1] + off, v0, v1);
                st_cluster_b64(peer_rh[2] + off, v0, v1);
            }
        }
        CLUSTER_SYNC();   // full rh visible everywhere

        // ---- pass 3: hn-dots (own cols, 1 row per task) ---------------------
        const int m_b0 = 128;                       // 8q x 8seg16 x 2row
        const int m_b1 = a1 ? 64 : 0;               // 8q x 4seg64 x 2row
        const int m_b2 = a2 ? 96 : 0;               // 8q x 6seg64 x 2row
        const int m_b3 = a3 ? 128 : 0;              // 8q x 8seg64 x 2row
        const int total3 = m_b0 + m_b1 + m_b2 + m_b3;

        for (int task = tid; task < total3; task += 512) {
            int tk = task;
            float A[4] = {0,0,0,0};
            float4 B = {0,0,0,0};
            float* dst;

            if (tk < m_b0) {
                const int row = tk & 1; tk >>= 1;
                const int q = tk & 7, seg = tk >> 3;
                const int c = q * 4, gc = rank * 32 + c;
                const size_t xr = row ? xr1 : xr0;
                if (seg == 0) B = *(const float4*)&xt[xr + gc];
                dot_s41<16, 32>(ch0_s + seg * 16 * 32 + c,
                                rh_s + row * 1280 + seg * 16, A);
                dst = hacc + row * 512 + gc;
            } else if ((tk -= m_b0) < m_b1) {
                const int row = tk & 1; tk >>= 1;
                const int q = tk & 7, seg = tk >> 3;
                const int c = q * 4, gc = 128 + rank * 32 + c;
                const size_t xr = row ? xr1 : xr0;
                if (seg == 0) B = *(const float4*)&xt[xr + gc];
                dot_s41<64, 32>(ch1_s + seg * 64 * 32 + c,
                                rh_s + row * 1280 + 128 + seg * 64, A);
                dst = hacc + row * 512 + gc;
            } else if ((tk -= m_b1) < m_b2) {
                const int row = tk & 1; tk >>= 1;
                const int q = tk & 7, seg = tk >> 3;
                const int lc = rank * 32 + q * 4, gc = 256 + lc;
                const size_t xr = row ? xr1 : xr0;
                if (seg == 0) B = *(const float4*)&xt[xr + gc];
                dot_g41_64(ch2 + (size_t)(seg * 64) * 128 + lc, 128,
                           rh_s + row * 1280 + 384 + seg * 64, A);
                dst = hacc + row * 512 + gc;
            } else {
                tk -= m_b2;
                const int row = tk & 1; tk >>= 1;
                const int q = tk & 7, seg = tk >> 3;
                const int lc = rank * 32 + q * 4, gc = 384 + lc;
                const size_t xr = row ? xr1 : xr0;
                if (seg == 0) B = *(const float4*)&xt[xr + gc];
                dot_g41_64(ch3 + (size_t)(seg * 64) * 128 + lc, 128,
                           rh_s + row * 1280 + 768 + seg * 64, A);
                dst = hacc + row * 512 + gc;
            }
            atomic4(dst, A, B);
        }
        __syncthreads();

        // ---- pass 4: gates + h update (own active cols) ---------------------
        {
            const int npairs = na * 16;    // per row
            for (int s = tid; s < 2 * npairs; s += 512) {
                const int row = s & 1;
                const int p = s >> 1;
                const int i = act[p >> 4];
                const int c = (p & 15) * 2;
                const int gc = i * 128 + rank * 32 + c;
                float* hh = h_s + row * 512;
                const float z0  = sigmoidf_(zacc[row * 512 + gc]);
                const float z1  = sigmoidf_(zacc[row * 512 + gc + 1]);
                const float n0  = sigmoidf_(hacc[row * 512 + gc]);
                const float n1  = sigmoidf_(hacc[row * 512 + gc + 1]);
                const float v0 = z0 * n0 + (1.0f - z0) * hh[gc];
                const float v1 = z1 * n1 + (1.0f - z1) * hh[gc + 1];
                hh[gc] = v0; hh[gc + 1] = v1;
                const uint32_t off = (uint32_t)(row * 512 + gc) * 4u;
                st_cluster_b64(peer_h[0] + off, v0, v1);
                st_cluster_b64(peer_h[1] + off, v0, v1);
                st_cluster_b64(peer_h[2] + off, v0, v1);
            }
        }
        __syncthreads();

        // ---- output: own 128 cols x 2 rows ----------------------------------
        if (tid < 256) {
            const int row = tid >> 7;
            const int idx = tid & 127;
            const int i = idx >> 5, c = idx & 31;
            const int gc = i * 128 + rank * 32 + c;
            const size_t xr = row ? xr1 : xr0;
            out[xr + gc] = h_s[row * 512 + gc];
        }
        CLUSTER_SYNC();   // full h visible for next step
    }
}

// ---------------------------------------------------------------------------
extern "C" void kernel_launch(void* const* d_in, const int* in_sizes, int n_in,
                              void* d_out, int out_size) {
    (void)in_sizes; (void)n_in; (void)out_size;
    const float* x  = (const float*)d_in[0];
    const float* W  = (const float*)d_in[1];
    const float* bb = (const float*)d_in[2];
    const float* Wr = (const float*)d_in[3];
    const float* br = (const float*)d_in[4];
    const float* Wz = (const float*)d_in[5];
    const float* bz = (const float*)d_in[6];
    const float* ch[4]; const float* cr[4]; const float* cz[4];
    for (int i = 0; i < 4; i++) {
        ch[i] = (const float*)d_in[7 + 3 * i + 0];
        cr[i] = (const float*)d_in[7 + 3 * i + 1];
        cz[i] = (const float*)d_in[7 + 3 * i + 2];
    }
    float* out = (float*)d_out;

    dim3 grid(GN / BN, GM / BM, 3);
    gemm3_kernel<<<grid, 256>>>(x, W, bb, Wr, br, Wz, bz);

    size_t smem_bytes = 53248 * sizeof(float);   // 212,992 B
    cudaFuncSetAttribute(scan_kernel,
                         cudaFuncAttributeMaxDynamicSharedMemorySize,
                         (int)smem_bytes);
    scan_kernel<<<(NBATCH / 2) * 4, 512, smem_bytes>>>(
        ch[0], cr[0], cz[0],
        ch[1], cr[1], cz[1],
        ch[2], cr[2], cz[2],
        ch[3], cr[3], cz[3],
        out);
}